// round 2
// baseline (speedup 1.0000x reference)
#include <cuda_runtime.h>
#include <math.h>
#include <float.h>

// Problem constants
#define NPIX 65536      // B*H*W
#define BB   16
#define DD   512
#define HW   4096
#define MM   512

// Output offsets (floats), tuple order: upd_q, upd_mem, s_query, s_memory, separateness, compactness
#define OFF_UPDQ   ((size_t)0)
#define OFF_UPDMEM ((size_t)67108864)
#define OFF_SQ     ((size_t)67371008)
#define OFF_SM     ((size_t)100925440)
#define OFF_SEP    ((size_t)134479872)
#define OFF_COMP   ((size_t)134479873)

// Scratch (static device memory; no allocations)
__device__ float g_invnorm[NPIX];
__device__ float g_colmax[MM];
__device__ float g_colinv[MM];
__device__ float g_partmax[128 * MM];
__device__ float g_partsum[128 * MM];
__device__ int   g_top1[NPIX];
__device__ int   g_top2[NPIX];
__device__ float g_wgt[NPIX];
__device__ float g_qupd[MM * DD];
__device__ float g_partc[256];
__device__ float g_parth[256];

// ---------------- normalize ----------------
__global__ void k_norm(const float* __restrict__ q) {
    int i  = blockIdx.x * blockDim.x + threadIdx.x;   // pixel id
    int b  = i >> 12;
    int hw = i & 4095;
    const float* p = q + (size_t)b * DD * HW + hw;
    float s = 0.f;
#pragma unroll 8
    for (int d = 0; d < DD; d++) {
        float v = p[(size_t)d * HW];
        s += v * v;
    }
    g_invnorm[i] = 1.0f / fmaxf(sqrtf(s), 1e-12f);
}

// write qn into upd_q first half (channel-major, stride 2D between channels)
__global__ void k_scale(const float* __restrict__ q, float* __restrict__ updq) {
    long long idx = (long long)blockIdx.x * blockDim.x + threadIdx.x;  // over B*D*HW
    int hw   = (int)(idx & 4095);
    int rest = (int)(idx >> 12);
    int d    = rest & 511;
    int b    = rest >> 9;
    float v = q[idx] * g_invnorm[(b << 12) + hw];
    updq[((size_t)(b * 1024 + d)) * HW + hw] = v;
}

// ---------------- GEMM1: S[n,m] = sum_d qn[n,d] * keys[m,d] ----------------
__global__ void __launch_bounds__(256) k_gemm1(const float* __restrict__ qn,
                                               const float* __restrict__ keys,
                                               float* __restrict__ S) {
    __shared__ float As[16][132];
    __shared__ float Bs[16][132];
    int tid = threadIdx.x;
    int tx = tid & 15, ty = tid >> 4;     // tx -> m (cols), ty -> n (rows)
    int m0 = blockIdx.x * 128;
    int n0 = blockIdx.y * 128;
    int b = n0 >> 12, hw0 = n0 & 4095;
    const float* Abase = qn + (size_t)b * 1024 * HW + hw0;

    float acc[8][8];
#pragma unroll
    for (int j = 0; j < 8; j++)
#pragma unroll
        for (int i = 0; i < 8; i++) acc[j][i] = 0.f;

    for (int k0 = 0; k0 < DD; k0 += 16) {
#pragma unroll
        for (int r = 0; r < 8; r++) {
            int idx = tid + 256 * r;
            int kk = idx >> 7, nn = idx & 127;
            As[kk][nn] = Abase[(size_t)(k0 + kk) * HW + nn];
        }
#pragma unroll
        for (int r = 0; r < 2; r++) {
            int idx = tid + 256 * r;
            int mm = idx >> 2, q4 = idx & 3;
            float4 v = *(const float4*)(keys + (size_t)(m0 + mm) * DD + k0 + q4 * 4);
            Bs[q4 * 4 + 0][mm] = v.x;
            Bs[q4 * 4 + 1][mm] = v.y;
            Bs[q4 * 4 + 2][mm] = v.z;
            Bs[q4 * 4 + 3][mm] = v.w;
        }
        __syncthreads();
#pragma unroll
        for (int kk = 0; kk < 16; kk++) {
            float ra[8], rb[8];
#pragma unroll
            for (int j = 0; j < 8; j++) ra[j] = As[kk][ty * 8 + j];
#pragma unroll
            for (int i = 0; i < 8; i++) rb[i] = Bs[kk][tx * 8 + i];
#pragma unroll
            for (int j = 0; j < 8; j++)
#pragma unroll
                for (int i = 0; i < 8; i++) acc[j][i] += ra[j] * rb[i];
        }
        __syncthreads();
    }
#pragma unroll
    for (int j = 0; j < 8; j++) {
        size_t row = (size_t)(n0 + ty * 8 + j) * MM + m0 + tx * 8;
        *(float4*)(S + row)     = make_float4(acc[j][0], acc[j][1], acc[j][2], acc[j][3]);
        *(float4*)(S + row + 4) = make_float4(acc[j][4], acc[j][5], acc[j][6], acc[j][7]);
    }
}

// ---------------- row softmax + top2 ----------------
__device__ __forceinline__ void merge2(float& m1, int& i1, float& m2, int& i2,
                                       float b1, int bi1, float b2, int bi2) {
    if (b1 > m1 || (b1 == m1 && bi1 < i1)) {
        float om1 = m1; int oi1 = i1;
        m1 = b1; i1 = bi1;
        if (b2 > om1 || (b2 == om1 && bi2 < oi1)) { m2 = b2; i2 = bi2; }
        else { m2 = om1; i2 = oi1; }
    } else {
        if (b1 > m2 || (b1 == m2 && bi1 < i2)) { m2 = b1; i2 = bi1; }
    }
}

__global__ void k_rowsm(const float* __restrict__ S, float* __restrict__ SM) {
    int warp = threadIdx.x >> 5, lane = threadIdx.x & 31;
    int n = blockIdx.x * 8 + warp;
    const float* row = S + (size_t)n * MM;

    float v[16];
    float m1 = -FLT_MAX, m2 = -FLT_MAX;
    int i1 = 0x7fffffff, i2 = 0x7fffffff;
#pragma unroll
    for (int j = 0; j < 16; j++) {
        float val = row[lane + 32 * j];
        v[j] = val;
        int idx = lane + 32 * j;
        if (val > m1 || (val == m1 && idx < i1)) { m2 = m1; i2 = i1; m1 = val; i1 = idx; }
        else if (val > m2 || (val == m2 && idx < i2)) { m2 = val; i2 = idx; }
    }
#pragma unroll
    for (int off = 16; off; off >>= 1) {
        float b1 = __shfl_xor_sync(0xffffffffu, m1, off);
        int  bi1 = __shfl_xor_sync(0xffffffffu, i1, off);
        float b2 = __shfl_xor_sync(0xffffffffu, m2, off);
        int  bi2 = __shfl_xor_sync(0xffffffffu, i2, off);
        merge2(m1, i1, m2, i2, b1, bi1, b2, bi2);
    }
    float rmax = m1;
    float s = 0.f;
#pragma unroll
    for (int j = 0; j < 16; j++) {
        v[j] = expf(v[j] - rmax);
        s += v[j];
    }
#pragma unroll
    for (int off = 16; off; off >>= 1) s += __shfl_xor_sync(0xffffffffu, s, off);
    float inv = 1.0f / s;
    float* orow = SM + (size_t)n * MM;
#pragma unroll
    for (int j = 0; j < 16; j++) orow[lane + 32 * j] = v[j] * inv;
    if (lane == 0) { g_top1[n] = i1; g_top2[n] = i2; }
}

// ---------------- column stats ----------------
__global__ void k_colmax_part(const float* __restrict__ S) {
    int t = threadIdx.x;
    const float* p = S + (size_t)blockIdx.x * 512 * MM + t;
    float m = -FLT_MAX;
    for (int r = 0; r < 512; r++) m = fmaxf(m, p[(size_t)r * MM]);
    g_partmax[blockIdx.x * MM + t] = m;
}
__global__ void k_colmax_red() {
    int t = threadIdx.x;
    float m = -FLT_MAX;
    for (int b = 0; b < 128; b++) m = fmaxf(m, g_partmax[b * MM + t]);
    g_colmax[t] = m;
}
__global__ void k_colsum_part(const float* __restrict__ S) {
    int t = threadIdx.x;
    float cm = g_colmax[t];
    const float* p = S + (size_t)blockIdx.x * 512 * MM + t;
    float s = 0.f;
    for (int r = 0; r < 512; r++) s += expf(p[(size_t)r * MM] - cm);
    g_partsum[blockIdx.x * MM + t] = s;
}
__global__ void k_colsum_red() {
    int t = threadIdx.x;
    float s = 0.f;
    for (int b = 0; b < 128; b++) s += g_partsum[b * MM + t];
    g_colinv[t] = 1.0f / s;
}

// wgt[n] = (s_query / colmax(s_query))[n, top1[n]] = exp(S[n,g] - colmax[g])
__global__ void k_wgt(const float* __restrict__ S) {
    int n = blockIdx.x * blockDim.x + threadIdx.x;
    int g = g_top1[n];
    g_wgt[n] = expf(S[(size_t)n * MM + g] - g_colmax[g]);
}

// in-place transform raw scores -> s_query
__global__ void k_sq(float* __restrict__ S) {
    long long idx = (long long)blockIdx.x * blockDim.x + threadIdx.x;
    int m = (int)(idx & 511);
    S[idx] = expf(S[idx] - g_colmax[m]) * g_colinv[m];
}

// ---------------- GEMM2: C[n,d] = sum_m sm[n,m]*keys[m,d] -> upd_q second half ----------------
__global__ void __launch_bounds__(256) k_gemm2(const float* __restrict__ SM,
                                               const float* __restrict__ keys,
                                               float* __restrict__ out) {
    __shared__ float As[16][132];
    __shared__ float Bs[16][132];
    int tid = threadIdx.x;
    int tx = tid & 15, ty = tid >> 4;     // tx -> n (rows, contiguous), ty -> d (cols)
    int d0 = blockIdx.x * 128;
    int n0 = blockIdx.y * 128;
    int b = n0 >> 12, hw0 = n0 & 4095;

    float acc[8][8];                       // acc[j][i]: j -> d, i -> n
#pragma unroll
    for (int j = 0; j < 8; j++)
#pragma unroll
        for (int i = 0; i < 8; i++) acc[j][i] = 0.f;

    for (int k0 = 0; k0 < MM; k0 += 16) {
#pragma unroll
        for (int r = 0; r < 2; r++) {
            int idx = tid + 256 * r;
            int nn = idx >> 2, q4 = idx & 3;
            float4 v = *(const float4*)(SM + (size_t)(n0 + nn) * MM + k0 + q4 * 4);
            As[q4 * 4 + 0][nn] = v.x;
            As[q4 * 4 + 1][nn] = v.y;
            As[q4 * 4 + 2][nn] = v.z;
            As[q4 * 4 + 3][nn] = v.w;
        }
#pragma unroll
        for (int r = 0; r < 8; r++) {
            int idx = tid + 256 * r;
            int kk = idx >> 7, dd = idx & 127;
            Bs[kk][dd] = keys[(size_t)(k0 + kk) * DD + d0 + dd];
        }
        __syncthreads();
#pragma unroll
        for (int kk = 0; kk < 16; kk++) {
            float ra[8], rb[8];
#pragma unroll
            for (int i = 0; i < 8; i++) ra[i] = As[kk][tx * 8 + i];
#pragma unroll
            for (int j = 0; j < 8; j++) rb[j] = Bs[kk][ty * 8 + j];
#pragma unroll
            for (int j = 0; j < 8; j++)
#pragma unroll
                for (int i = 0; i < 8; i++) acc[j][i] += rb[j] * ra[i];
        }
        __syncthreads();
    }
#pragma unroll
    for (int j = 0; j < 8; j++) {
        int d = d0 + ty * 8 + j;
        size_t base = (size_t)(b * 1024 + 512 + d) * HW + hw0 + tx * 8;
        *(float4*)(out + base)     = make_float4(acc[j][0], acc[j][1], acc[j][2], acc[j][3]);
        *(float4*)(out + base + 4) = make_float4(acc[j][4], acc[j][5], acc[j][6], acc[j][7]);
    }
}

// ---------------- triplet stats ----------------
__global__ void k_triplet(const float* __restrict__ qn, const float* __restrict__ keys) {
    int n = blockIdx.x * 256 + threadIdx.x;
    int b = n >> 12, hw = n & 4095;
    const float* qp = qn + (size_t)b * 1024 * HW + hw;
    const float* kp = keys + (size_t)g_top1[n] * DD;
    const float* kn = keys + (size_t)g_top2[n] * DD;
    float ac = 0.f, ap = 0.f, an = 0.f;
#pragma unroll 4
    for (int d = 0; d < DD; d++) {
        float q = qp[(size_t)d * HW];
        float dp = q - kp[d];
        ac += dp * dp;
        float dpe = dp + 1e-6f;
        ap += dpe * dpe;
        float dne = q - kn[d] + 1e-6f;
        an += dne * dne;
    }
    float hinge = fmaxf(sqrtf(ap) - sqrtf(an) + 1.0f, 0.f);
    __shared__ float sc[256], sh[256];
    int t = threadIdx.x;
    sc[t] = ac; sh[t] = hinge;
    __syncthreads();
    for (int s = 128; s > 0; s >>= 1) {
        if (t < s) { sc[t] += sc[t + s]; sh[t] += sh[t + s]; }
        __syncthreads();
    }
    if (t == 0) { g_partc[blockIdx.x] = sc[0]; g_parth[blockIdx.x] = sh[0]; }
}

__global__ void k_final(float* __restrict__ out) {
    __shared__ double dc[256], dh[256];
    int t = threadIdx.x;
    dc[t] = (double)g_partc[t];
    dh[t] = (double)g_parth[t];
    __syncthreads();
    for (int s = 128; s > 0; s >>= 1) {
        if (t < s) { dc[t] += dc[t + s]; dh[t] += dh[t + s]; }
        __syncthreads();
    }
    if (t == 0) {
        out[OFF_COMP] = (float)(dc[0] / (double)((size_t)NPIX * DD));
        out[OFF_SEP]  = (float)(dh[0] / (double)NPIX);
    }
}

// ---------------- segment sum update ----------------
__global__ void k_zeroq() {
    int i = blockIdx.x * blockDim.x + threadIdx.x;
    g_qupd[i] = 0.f;
}

__global__ void k_scatter(const float* __restrict__ qn) {
    int n = blockIdx.x * 256 + threadIdx.x;
    int b = n >> 12, hw = n & 4095;
    int g = g_top1[n];
    float w = g_wgt[n];
    const float* qp = qn + (size_t)b * 1024 * HW + hw;
    float* dst = g_qupd + (size_t)g * DD;
#pragma unroll 4
    for (int d = 0; d < DD; d++) {
        atomicAdd(&dst[d], w * qp[(size_t)d * HW]);
    }
}

__global__ void k_updmem(const float* __restrict__ keys, float* __restrict__ out) {
    int m = blockIdx.x, t = threadIdx.x;
    float u[4];
    float s = 0.f;
#pragma unroll
    for (int r = 0; r < 4; r++) {
        int d = t + 128 * r;
        float x = g_qupd[(size_t)m * DD + d] + keys[(size_t)m * DD + d];
        u[r] = x;
        s += x * x;
    }
    __shared__ float red[128];
    red[t] = s;
    __syncthreads();
    for (int k = 64; k > 0; k >>= 1) {
        if (t < k) red[t] += red[t + k];
        __syncthreads();
    }
    float inv = 1.0f / fmaxf(sqrtf(red[0]), 1e-12f);
#pragma unroll
    for (int r = 0; r < 4; r++) {
        int d = t + 128 * r;
        out[OFF_UPDMEM + (size_t)m * DD + d] = u[r] * inv;
    }
}

// ---------------- launch ----------------
extern "C" void kernel_launch(void* const* d_in, const int* in_sizes, int n_in,
                              void* d_out, int out_size) {
    const float* query = (const float*)d_in[0];
    const float* keys  = (const float*)d_in[1];
    float* out  = (float*)d_out;
    float* updq = out + OFF_UPDQ;
    float* sq   = out + OFF_SQ;   // holds raw scores until k_sq transforms it
    float* sm   = out + OFF_SM;

    k_norm<<<NPIX / 256, 256>>>(query);
    k_scale<<<(BB * DD * HW) / 256, 256>>>(query, updq);

    k_gemm1<<<dim3(MM / 128, NPIX / 128), 256>>>(updq, keys, sq);

    k_rowsm<<<NPIX / 8, 256>>>(sq, sm);

    k_colmax_part<<<128, 512>>>(sq);
    k_colmax_red<<<1, 512>>>();
    k_colsum_part<<<128, 512>>>(sq);
    k_colsum_red<<<1, 512>>>();
    k_wgt<<<NPIX / 256, 256>>>(sq);
    k_sq<<<(NPIX * (long long)MM) / 256, 256>>>(sq);

    k_gemm2<<<dim3(DD / 128, NPIX / 128), 256>>>(sm, keys, out);

    k_triplet<<<256, 256>>>(updq, keys);
    k_final<<<1, 256>>>(out);

    k_zeroq<<<(MM * DD) / 256, 256>>>();
    k_scatter<<<NPIX / 256, 256>>>(updq);
    k_updmem<<<MM, 128>>>(keys, out);
}

// round 7
// speedup vs baseline: 1.6374x; 1.6374x over previous
#include <cuda_runtime.h>
#include <cuda_bf16.h>
#include <math.h>
#include <float.h>
#include <stdint.h>

// Problem constants
#define NPIX 65536      // B*H*W
#define BB   16
#define DD   512
#define HW   4096
#define MM   512

// Output offsets (floats), tuple order: upd_q, upd_mem, s_query, s_memory, separateness, compactness
#define OFF_UPDQ   ((size_t)0)
#define OFF_UPDMEM ((size_t)67108864)
#define OFF_SQ     ((size_t)67371008)
#define OFF_SM     ((size_t)100925440)
#define OFF_SEP    ((size_t)134479872)
#define OFF_COMP   ((size_t)134479873)

// ---------------- scratch (static device memory) ----------------
__device__ float g_invnorm[NPIX];
__device__ float g_colmax[MM];
__device__ float g_colinv[MM];
__device__ float g_partmax[128 * MM];
__device__ float g_partsum[128 * MM];
__device__ int   g_top1[NPIX];
__device__ int   g_top2[NPIX];
__device__ float g_wgt[NPIX];
__device__ float g_qupd[MM * DD];
__device__ float g_partc[256];
__device__ float g_parth[256];

// bf16 hi/lo operands for tensor-core GEMMs (all [row][512] K-major)
__device__ __nv_bfloat16 g_qbf_hi[(size_t)NPIX * DD];
__device__ __nv_bfloat16 g_qbf_lo[(size_t)NPIX * DD];
__device__ __nv_bfloat16 g_smbf_hi[(size_t)NPIX * MM];
__device__ __nv_bfloat16 g_smbf_lo[(size_t)NPIX * MM];
__device__ __nv_bfloat16 g_keys_hi[MM * DD];
__device__ __nv_bfloat16 g_keys_lo[MM * DD];
__device__ __nv_bfloat16 g_keysT_hi[DD * MM];
__device__ __nv_bfloat16 g_keysT_lo[DD * MM];

// ---------------- helpers ----------------
__device__ __forceinline__ uint32_t smem_u32(const void* p) {
    uint32_t a;
    asm("{ .reg .u64 t; cvta.to.shared.u64 t, %1; cvt.u32.u64 %0, t; }" : "=r"(a) : "l"(p));
    return a;
}
#define SWZ(x) ((x) ^ (((x) >> 3) & 0x70))

__device__ __forceinline__ void cp16(uint32_t dst, const void* src) {
    asm volatile("cp.async.cg.shared.global [%0], [%1], 16;"
                 :: "r"(dst), "l"(__cvta_generic_to_global(src)));
}
#define CP_COMMIT() asm volatile("cp.async.commit_group;" ::: "memory")
#define CP_WAIT(n)  asm volatile("cp.async.wait_group %0;" :: "n"(n) : "memory")

__device__ __forceinline__ void ldsm4(uint32_t* r, uint32_t addr) {
    asm volatile("ldmatrix.sync.aligned.m8n8.x4.shared.b16 {%0,%1,%2,%3}, [%4];"
                 : "=r"(r[0]), "=r"(r[1]), "=r"(r[2]), "=r"(r[3]) : "r"(addr));
}
__device__ __forceinline__ void mma16816(float* c, const uint32_t* a, uint32_t b0, uint32_t b1) {
    asm volatile("mma.sync.aligned.m16n8k16.row.col.f32.bf16.bf16.f32 "
                 "{%0,%1,%2,%3}, {%4,%5,%6,%7}, {%8,%9}, {%0,%1,%2,%3};"
                 : "+f"(c[0]), "+f"(c[1]), "+f"(c[2]), "+f"(c[3])
                 : "r"(a[0]), "r"(a[1]), "r"(a[2]), "r"(a[3]), "r"(b0), "r"(b1));
}

__device__ __forceinline__ void bf16_split(float v, __nv_bfloat16& hi, __nv_bfloat16& lo) {
    hi = __float2bfloat16(v);
    lo = __float2bfloat16(v - __bfloat162float(hi));
}

// ---------------- normalize ----------------
__global__ void k_norm(const float* __restrict__ q) {
    int i  = blockIdx.x * blockDim.x + threadIdx.x;
    int b  = i >> 12;
    int hw = i & 4095;
    const float* p = q + (size_t)b * DD * HW + hw;
    float s = 0.f;
#pragma unroll 8
    for (int d = 0; d < DD; d++) {
        float v = p[(size_t)d * HW];
        s += v * v;
    }
    g_invnorm[i] = 1.0f / fmaxf(sqrtf(s), 1e-12f);
}

// normalize -> updq (channel-major f32) + qbf hi/lo ([n][d] bf16, via tile transpose)
__global__ void k_prep_q(const float* __restrict__ q, float* __restrict__ updq) {
    __shared__ float t[32][33];
    int b = blockIdx.z, d0 = blockIdx.y * 32, hw0 = blockIdx.x * 32;
    int tx = threadIdx.x & 31, ty = threadIdx.x >> 5;
    float inv = g_invnorm[(b << 12) + hw0 + tx];
#pragma unroll
    for (int r = 0; r < 4; r++) {
        int d = d0 + ty + 8 * r;
        float v = q[((size_t)b * 512 + d) * 4096 + hw0 + tx] * inv;
        updq[((size_t)b * 1024 + d) * 4096 + hw0 + tx] = v;
        t[ty + 8 * r][tx] = v;
    }
    __syncthreads();
#pragma unroll
    for (int r = 0; r < 4; r++) {
        int hw = ty + 8 * r;
        float v = t[tx][hw];
        int n = (b << 12) + hw0 + hw;
        __nv_bfloat16 hi, lo;
        bf16_split(v, hi, lo);
        g_qbf_hi[(size_t)n * 512 + d0 + tx] = hi;
        g_qbf_lo[(size_t)n * 512 + d0 + tx] = lo;
    }
}

__global__ void k_prep_keys(const float* __restrict__ keys) {
    int m = blockIdx.x, d = threadIdx.x;
    float v = keys[m * 512 + d];
    __nv_bfloat16 hi, lo;
    bf16_split(v, hi, lo);
    g_keys_hi[m * 512 + d] = hi;
    g_keys_lo[m * 512 + d] = lo;
    g_keysT_hi[d * 512 + m] = hi;
    g_keysT_lo[d * 512 + m] = lo;
}

// ---------------- mma.sync GEMM: 128x128 tile, K=512, bf16 hi/lo 3-term ----------------
// mode 0: A=qbf,  B=keys  -> S[n][m] row-major
// mode 1: A=smbf, B=keysT -> upd_q second half (channel-major)
#define OFS_AH 0
#define OFS_AL 16384
#define OFS_BH 32768
#define OFS_BL 49152
#define STAGE  65536

__global__ void __launch_bounds__(256) k_mma_gemm(float* __restrict__ out, int mode) {
    extern __shared__ char smem[];
    uint32_t sb = smem_u32(smem);
    int tid = threadIdx.x;
    int col0 = blockIdx.x * 128;     // output column block (m or d)
    int n0   = blockIdx.y * 128;     // pixel block

    const __nv_bfloat16* Ahi = mode ? g_smbf_hi : g_qbf_hi;
    const __nv_bfloat16* Alo = mode ? g_smbf_lo : g_qbf_lo;
    const __nv_bfloat16* Bhi = mode ? g_keysT_hi : g_keys_hi;
    const __nv_bfloat16* Blo = mode ? g_keysT_lo : g_keys_lo;

    // stage loader: 4 tiles x 128 rows x 64 bf16
    auto load_stage = [&](int buf, int k0) {
        uint32_t base = sb + buf * STAGE;
#pragma unroll
        for (int i = 0; i < 4; i++) {
            int idx = tid + 256 * i;
            int r = idx >> 3, kb = idx & 7;
            uint32_t so = SWZ((uint32_t)(r * 128 + kb * 16));
            const size_t sa = (size_t)(n0 + r) * 512 + k0 + kb * 8;
            const size_t sbx = (size_t)(col0 + r) * 512 + k0 + kb * 8;
            cp16(base + OFS_AH + so, Ahi + sa);
            cp16(base + OFS_AL + so, Alo + sa);
            cp16(base + OFS_BH + so, Bhi + sbx);
            cp16(base + OFS_BL + so, Blo + sbx);
        }
    };

    int lane = tid & 31;
    int wm = (tid >> 5) & 1;          // 2 warps in m
    int wn = (tid >> 5) >> 1;         // 4 warps in n
    int lrow = lane & 15, lhalf = lane >> 4;

    uint32_t arow[4], brow[2];
#pragma unroll
    for (int mf = 0; mf < 4; mf++) arow[mf] = (uint32_t)((wm * 64 + mf * 16 + lrow) * 128 + lhalf * 16);
#pragma unroll
    for (int ng = 0; ng < 2; ng++)  brow[ng] = (uint32_t)((wn * 32 + ng * 16 + lrow) * 128 + lhalf * 16);

    float C[4][4][4];
#pragma unroll
    for (int a = 0; a < 4; a++)
#pragma unroll
        for (int b = 0; b < 4; b++)
#pragma unroll
            for (int c = 0; c < 4; c++) C[a][b][c] = 0.f;

    load_stage(0, 0);   CP_COMMIT();
    load_stage(1, 64);  CP_COMMIT();

#pragma unroll 1
    for (int ch = 0; ch < 8; ch++) {
        if (ch < 7) { CP_WAIT(1); } else { CP_WAIT(0); }
        __syncthreads();
        uint32_t base = sb + (ch & 1) * STAGE;
#pragma unroll
        for (int ks = 0; ks < 4; ks++) {
            uint32_t kofs = (uint32_t)(ks * 32);
            uint32_t ah[4][4], al[4][4];
#pragma unroll
            for (int mf = 0; mf < 4; mf++) {
                uint32_t off = arow[mf] + kofs;
                uint32_t sw = SWZ(off);
                ldsm4(ah[mf], base + OFS_AH + sw);
                ldsm4(al[mf], base + OFS_AL + sw);
            }
            uint32_t bh[2][4], bl[2][4];
#pragma unroll
            for (int ng = 0; ng < 2; ng++) {
                uint32_t off = brow[ng] + kofs;
                uint32_t sw = SWZ(off);
                ldsm4(bh[ng], base + OFS_BH + sw);
                ldsm4(bl[ng], base + OFS_BL + sw);
            }
#pragma unroll
            for (int mf = 0; mf < 4; mf++) {
#pragma unroll
                for (int nf = 0; nf < 4; nf++) {
                    int g = nf >> 1, h = nf & 1;
                    mma16816(C[mf][nf], ah[mf], bh[g][h], bh[g][h + 2]);
                    mma16816(C[mf][nf], ah[mf], bl[g][h], bl[g][h + 2]);
                    mma16816(C[mf][nf], al[mf], bh[g][h], bh[g][h + 2]);
                }
            }
        }
        __syncthreads();
        if (ch < 6) { load_stage(ch & 1, (ch + 2) * 64); CP_COMMIT(); }
    }

    // epilogue: frags -> smem [row][132] -> coalesced gmem
    float* fs = (float*)smem;
#pragma unroll
    for (int mf = 0; mf < 4; mf++) {
#pragma unroll
        for (int nf = 0; nf < 4; nf++) {
            int gcol = wn * 32 + (nf >> 1) * 16 + (nf & 1) * 8 + 2 * (lane & 3);
            int grow = wm * 64 + mf * 16 + (lane >> 2);
            *(float2*)&fs[grow * 132 + gcol]       = make_float2(C[mf][nf][0], C[mf][nf][1]);
            *(float2*)&fs[(grow + 8) * 132 + gcol] = make_float2(C[mf][nf][2], C[mf][nf][3]);
        }
    }
    __syncthreads();
    if (mode == 0) {
#pragma unroll 1
        for (int i = 0; i < 64; i++) {
            int idx = i * 256 + tid;
            int row = idx >> 7, col = idx & 127;
            out[(size_t)(n0 + row) * 512 + col0 + col] = fs[row * 132 + col];
        }
    } else {
        int b = n0 >> 12, hw0 = n0 & 4095;
#pragma unroll 1
        for (int i = 0; i < 64; i++) {
            int idx = i * 256 + tid;
            int c = idx >> 7, r = idx & 127;
            out[((size_t)(b * 1024 + 512 + col0 + c)) * 4096 + hw0 + r] = fs[r * 132 + c];
        }
    }
}

// ---------------- row softmax + top2 (+ bf16 hi/lo of probs) ----------------
__device__ __forceinline__ void merge2(float& m1, int& i1, float& m2, int& i2,
                                       float b1, int bi1, float b2, int bi2) {
    if (b1 > m1 || (b1 == m1 && bi1 < i1)) {
        float om1 = m1; int oi1 = i1;
        m1 = b1; i1 = bi1;
        if (b2 > om1 || (b2 == om1 && bi2 < oi1)) { m2 = b2; i2 = bi2; }
        else { m2 = om1; i2 = oi1; }
    } else {
        if (b1 > m2 || (b1 == m2 && bi1 < i2)) { m2 = b1; i2 = bi1; }
    }
}

__global__ void k_rowsm(const float* __restrict__ S, float* __restrict__ SM) {
    int warp = threadIdx.x >> 5, lane = threadIdx.x & 31;
    int n = blockIdx.x * 8 + warp;
    const float* row = S + (size_t)n * MM;

    float v[16];
    float m1 = -FLT_MAX, m2 = -FLT_MAX;
    int i1 = 0x7fffffff, i2 = 0x7fffffff;
#pragma unroll
    for (int j = 0; j < 16; j++) {
        float val = row[lane + 32 * j];
        v[j] = val;
        int idx = lane + 32 * j;
        if (val > m1 || (val == m1 && idx < i1)) { m2 = m1; i2 = i1; m1 = val; i1 = idx; }
        else if (val > m2 || (val == m2 && idx < i2)) { m2 = val; i2 = idx; }
    }
#pragma unroll
    for (int off = 16; off; off >>= 1) {
        float b1 = __shfl_xor_sync(0xffffffffu, m1, off);
        int  bi1 = __shfl_xor_sync(0xffffffffu, i1, off);
        float b2 = __shfl_xor_sync(0xffffffffu, m2, off);
        int  bi2 = __shfl_xor_sync(0xffffffffu, i2, off);
        merge2(m1, i1, m2, i2, b1, bi1, b2, bi2);
    }
    float rmax = m1;
    float s = 0.f;
#pragma unroll
    for (int j = 0; j < 16; j++) {
        v[j] = expf(v[j] - rmax);
        s += v[j];
    }
#pragma unroll
    for (int off = 16; off; off >>= 1) s += __shfl_xor_sync(0xffffffffu, s, off);
    float inv = 1.0f / s;
    float* orow = SM + (size_t)n * MM;
#pragma unroll
    for (int j = 0; j < 16; j++) {
        float p = v[j] * inv;
        orow[lane + 32 * j] = p;
        __nv_bfloat16 hi, lo;
        bf16_split(p, hi, lo);
        g_smbf_hi[(size_t)n * 512 + lane + 32 * j] = hi;
        g_smbf_lo[(size_t)n * 512 + lane + 32 * j] = lo;
    }
    if (lane == 0) { g_top1[n] = i1; g_top2[n] = i2; }
}

// ---------------- column stats ----------------
__global__ void k_colmax_part(const float* __restrict__ S) {
    int t = threadIdx.x;
    const float* p = S + (size_t)blockIdx.x * 512 * MM + t;
    float m = -FLT_MAX;
    for (int r = 0; r < 512; r++) m = fmaxf(m, p[(size_t)r * MM]);
    g_partmax[blockIdx.x * MM + t] = m;
}
__global__ void k_colmax_red() {
    int t = threadIdx.x;
    float m = -FLT_MAX;
    for (int b = 0; b < 128; b++) m = fmaxf(m, g_partmax[b * MM + t]);
    g_colmax[t] = m;
}
__global__ void k_colsum_part(const float* __restrict__ S) {
    int t = threadIdx.x;
    float cm = g_colmax[t];
    const float* p = S + (size_t)blockIdx.x * 512 * MM + t;
    float s = 0.f;
    for (int r = 0; r < 512; r++) s += expf(p[(size_t)r * MM] - cm);
    g_partsum[blockIdx.x * MM + t] = s;
}
__global__ void k_colsum_red() {
    int t = threadIdx.x;
    float s = 0.f;
    for (int b = 0; b < 128; b++) s += g_partsum[b * MM + t];
    g_colinv[t] = 1.0f / s;
}

__global__ void k_wgt(const float* __restrict__ S) {
    int n = blockIdx.x * blockDim.x + threadIdx.x;
    int g = g_top1[n];
    g_wgt[n] = expf(S[(size_t)n * MM + g] - g_colmax[g]);
}

__global__ void k_sq(float* __restrict__ S) {
    long long idx = (long long)blockIdx.x * blockDim.x + threadIdx.x;
    int m = (int)(idx & 511);
    S[idx] = expf(S[idx] - g_colmax[m]) * g_colinv[m];
}

// ---------------- triplet stats ----------------
__global__ void k_triplet(const float* __restrict__ qn, const float* __restrict__ keys) {
    int n = blockIdx.x * 256 + threadIdx.x;
    int b = n >> 12, hw = n & 4095;
    const float* qp = qn + (size_t)b * 1024 * HW + hw;
    const float* kp = keys + (size_t)g_top1[n] * DD;
    const float* kn = keys + (size_t)g_top2[n] * DD;
    float ac = 0.f, ap = 0.f, an = 0.f;
#pragma unroll 4
    for (int d = 0; d < DD; d++) {
        float q = qp[(size_t)d * HW];
        float dp = q - kp[d];
        ac += dp * dp;
        float dpe = dp + 1e-6f;
        ap += dpe * dpe;
        float dne = q - kn[d] + 1e-6f;
        an += dne * dne;
    }
    float hinge = fmaxf(sqrtf(ap) - sqrtf(an) + 1.0f, 0.f);
    __shared__ float sc[256], sh[256];
    int t = threadIdx.x;
    sc[t] = ac; sh[t] = hinge;
    __syncthreads();
    for (int s = 128; s > 0; s >>= 1) {
        if (t < s) { sc[t] += sc[t + s]; sh[t] += sh[t + s]; }
        __syncthreads();
    }
    if (t == 0) { g_partc[blockIdx.x] = sc[0]; g_parth[blockIdx.x] = sh[0]; }
}

__global__ void k_final(float* __restrict__ out) {
    __shared__ double dc[256], dh[256];
    int t = threadIdx.x;
    dc[t] = (double)g_partc[t];
    dh[t] = (double)g_parth[t];
    __syncthreads();
    for (int s = 128; s > 0; s >>= 1) {
        if (t < s) { dc[t] += dc[t + s]; dh[t] += dh[t + s]; }
        __syncthreads();
    }
    if (t == 0) {
        out[OFF_COMP] = (float)(dc[0] / (double)((size_t)NPIX * DD));
        out[OFF_SEP]  = (float)(dh[0] / (double)NPIX);
    }
}

// ---------------- segment sum update ----------------
__global__ void k_zeroq() {
    int i = blockIdx.x * blockDim.x + threadIdx.x;
    g_qupd[i] = 0.f;
}

__global__ void k_scatter(const float* __restrict__ qn) {
    int n = blockIdx.x * 256 + threadIdx.x;
    int b = n >> 12, hw = n & 4095;
    int g = g_top1[n];
    float w = g_wgt[n];
    const float* qp = qn + (size_t)b * 1024 * HW + hw;
    float* dst = g_qupd + (size_t)g * DD;
#pragma unroll 4
    for (int d = 0; d < DD; d++) {
        atomicAdd(&dst[d], w * qp[(size_t)d * HW]);
    }
}

__global__ void k_updmem(const float* __restrict__ keys, float* __restrict__ out) {
    int m = blockIdx.x, t = threadIdx.x;
    float u[4];
    float s = 0.f;
#pragma unroll
    for (int r = 0; r < 4; r++) {
        int d = t + 128 * r;
        float x = g_qupd[(size_t)m * DD + d] + keys[(size_t)m * DD + d];
        u[r] = x;
        s += x * x;
    }
    __shared__ float red[128];
    red[t] = s;
    __syncthreads();
    for (int k = 64; k > 0; k >>= 1) {
        if (t < k) red[t] += red[t + k];
        __syncthreads();
    }
    float inv = 1.0f / fmaxf(sqrtf(red[0]), 1e-12f);
#pragma unroll
    for (int r = 0; r < 4; r++) {
        int d = t + 128 * r;
        out[OFF_UPDMEM + (size_t)m * DD + d] = u[r] * inv;
    }
}

// ---------------- launch ----------------
#define GEMM_SMEM 131072

extern "C" void kernel_launch(void* const* d_in, const int* in_sizes, int n_in,
                              void* d_out, int out_size) {
    const float* query = (const float*)d_in[0];
    const float* keys  = (const float*)d_in[1];
    float* out  = (float*)d_out;
    float* updq = out + OFF_UPDQ;
    float* sq   = out + OFF_SQ;   // raw scores until k_sq transforms them
    float* sm   = out + OFF_SM;

    cudaFuncSetAttribute(k_mma_gemm, cudaFuncAttributeMaxDynamicSharedMemorySize, GEMM_SMEM);

    k_norm<<<NPIX / 256, 256>>>(query);
    k_prep_q<<<dim3(HW / 32, DD / 32, BB), 256>>>(query, updq);
    k_prep_keys<<<MM, DD>>>(keys);

    // GEMM1: raw scores S[n][m]
    k_mma_gemm<<<dim3(MM / 128, NPIX / 128), 256, GEMM_SMEM>>>(sq, 0);

    k_rowsm<<<NPIX / 8, 256>>>(sq, sm);

    k_colmax_part<<<128, 512>>>(sq);
    k_colmax_red<<<1, 512>>>();
    k_colsum_part<<<128, 512>>>(sq);
    k_colsum_red<<<1, 512>>>();
    k_wgt<<<NPIX / 256, 256>>>(sq);
    k_sq<<<(NPIX * (long long)MM) / 256, 256>>>(sq);

    // GEMM2: concat_mem -> upd_q second half
    k_mma_gemm<<<dim3(DD / 128, NPIX / 128), 256, GEMM_SMEM>>>(updq, 1);

    k_triplet<<<256, 256>>>(updq, keys);
    k_final<<<1, 256>>>(out);

    k_zeroq<<<(MM * DD) / 256, 256>>>();
    k_scatter<<<NPIX / 256, 256>>>(updq);
    k_updmem<<<MM, 128>>>(keys, out);
}

// round 11
// speedup vs baseline: 2.0373x; 1.2442x over previous
#include <cuda_runtime.h>
#include <cuda_bf16.h>
#include <math.h>
#include <float.h>
#include <stdint.h>

// Problem constants
#define NPIX 65536      // B*H*W
#define BB   16
#define DD   512
#define HW   4096
#define MM   512

// Output offsets (floats), tuple order: upd_q, upd_mem, s_query, s_memory, separateness, compactness
#define OFF_UPDQ   ((size_t)0)
#define OFF_UPDMEM ((size_t)67108864)
#define OFF_SQ     ((size_t)67371008)
#define OFF_SM     ((size_t)100925440)
#define OFF_SEP    ((size_t)134479872)
#define OFF_COMP   ((size_t)134479873)

// ---------------- scratch (static device memory) ----------------
__device__ float g_invnorm[NPIX];
__device__ float g_sumq[NPIX];
__device__ float g_m1[NPIX];
__device__ float g_m2[NPIX];
__device__ int   g_top1[NPIX];
__device__ int   g_top2[NPIX];
__device__ float g_wgt[NPIX];
__device__ float g_colsum[MM];
__device__ float g_cmx[MM];       // per-column max of exp(s)
__device__ float g_colinv[MM];
__device__ float g_sumk[MM];
__device__ float g_k2[MM];
__device__ float g_acc[2];        // 0: compactness sum, 1: separateness sum
__device__ __align__(16) float g_qupd[MM * DD];

// bf16 hi/lo operands for tensor-core GEMMs (all [row][512] K-major)
__device__ __nv_bfloat16 g_qbf_hi[(size_t)NPIX * DD];
__device__ __nv_bfloat16 g_qbf_lo[(size_t)NPIX * DD];
__device__ __nv_bfloat16 g_smbf_hi[(size_t)NPIX * MM];
__device__ __nv_bfloat16 g_smbf_lo[(size_t)NPIX * MM];
__device__ __nv_bfloat16 g_keys_hi[MM * DD];
__device__ __nv_bfloat16 g_keys_lo[MM * DD];
__device__ __nv_bfloat16 g_keysT_hi[DD * MM];
__device__ __nv_bfloat16 g_keysT_lo[DD * MM];

// ---------------- helpers ----------------
__device__ __forceinline__ uint32_t smem_u32(const void* p) {
    uint32_t a;
    asm("{ .reg .u64 t; cvta.to.shared.u64 t, %1; cvt.u32.u64 %0, t; }" : "=r"(a) : "l"(p));
    return a;
}
#define SWZ(x) ((x) ^ (((x) >> 3) & 0x70))

__device__ __forceinline__ void cp16(uint32_t dst, const void* src) {
    asm volatile("cp.async.cg.shared.global [%0], [%1], 16;"
                 :: "r"(dst), "l"(__cvta_generic_to_global(src)));
}
#define CP_COMMIT() asm volatile("cp.async.commit_group;" ::: "memory")
#define CP_WAIT(n)  asm volatile("cp.async.wait_group %0;" :: "n"(n) : "memory")

__device__ __forceinline__ void ldsm4(uint32_t* r, uint32_t addr) {
    asm volatile("ldmatrix.sync.aligned.m8n8.x4.shared.b16 {%0,%1,%2,%3}, [%4];"
                 : "=r"(r[0]), "=r"(r[1]), "=r"(r[2]), "=r"(r[3]) : "r"(addr));
}
__device__ __forceinline__ void mma16816(float* c, const uint32_t* a, uint32_t b0, uint32_t b1) {
    asm volatile("mma.sync.aligned.m16n8k16.row.col.f32.bf16.bf16.f32 "
                 "{%0,%1,%2,%3}, {%4,%5,%6,%7}, {%8,%9}, {%0,%1,%2,%3};"
                 : "+f"(c[0]), "+f"(c[1]), "+f"(c[2]), "+f"(c[3])
                 : "r"(a[0]), "r"(a[1]), "r"(a[2]), "r"(a[3]), "r"(b0), "r"(b1));
}
__device__ __forceinline__ void red_v4(float* dst, float a, float b, float c, float d) {
    asm volatile("red.global.add.v4.f32 [%0], {%1,%2,%3,%4};"
                 :: "l"(__cvta_generic_to_global(dst)), "f"(a), "f"(b), "f"(c), "f"(d) : "memory");
}

__device__ __forceinline__ void bf16_split(float v, __nv_bfloat16& hi, __nv_bfloat16& lo) {
    hi = __float2bfloat16(v);
    lo = __float2bfloat16(v - __bfloat162float(hi));
}

// ---------------- init (graph-replay safe zeroing) ----------------
__global__ void k_init() {
    int i = blockIdx.x * 256 + threadIdx.x;
    g_qupd[i] = 0.f;
    if (i < MM) { g_colsum[i] = 0.f; g_cmx[i] = 0.f; }
    if (i < 2) g_acc[i] = 0.f;
}

// ---------------- normalize: invnorm + sumq ----------------
__global__ void k_norm(const float* __restrict__ q) {
    int i  = blockIdx.x * blockDim.x + threadIdx.x;
    int b  = i >> 12;
    int hw = i & 4095;
    const float* p = q + (size_t)b * DD * HW + hw;
    float s2 = 0.f, s1 = 0.f;
#pragma unroll 8
    for (int d = 0; d < DD; d++) {
        float v = p[(size_t)d * HW];
        s2 += v * v;
        s1 += v;
    }
    float inv = 1.0f / fmaxf(sqrtf(s2), 1e-12f);
    g_invnorm[i] = inv;
    g_sumq[i] = s1 * inv;
}

// normalize -> updq (channel-major f32) + qbf hi/lo ([n][d] bf16, via tile transpose)
__global__ void k_prep_q(const float* __restrict__ q, float* __restrict__ updq) {
    __shared__ float t[32][33];
    int b = blockIdx.z, d0 = blockIdx.y * 32, hw0 = blockIdx.x * 32;
    int tx = threadIdx.x & 31, ty = threadIdx.x >> 5;
    float inv = g_invnorm[(b << 12) + hw0 + tx];
#pragma unroll
    for (int r = 0; r < 4; r++) {
        int d = d0 + ty + 8 * r;
        float v = q[((size_t)b * 512 + d) * 4096 + hw0 + tx] * inv;
        updq[((size_t)b * 1024 + d) * 4096 + hw0 + tx] = v;
        t[ty + 8 * r][tx] = v;
    }
    __syncthreads();
#pragma unroll
    for (int r = 0; r < 4; r++) {
        int hw = ty + 8 * r;
        float v = t[tx][hw];
        int n = (b << 12) + hw0 + hw;
        __nv_bfloat16 hi, lo;
        bf16_split(v, hi, lo);
        g_qbf_hi[(size_t)n * 512 + d0 + tx] = hi;
        g_qbf_lo[(size_t)n * 512 + d0 + tx] = lo;
    }
}

// keys -> bf16 hi/lo [m][d] + transposed [d][m] + per-key sum / norm^2
__global__ void k_prep_keys(const float* __restrict__ keys) {
    __shared__ float rs[512], rq[512];
    int m = blockIdx.x, d = threadIdx.x;
    float v = keys[m * 512 + d];
    __nv_bfloat16 hi, lo;
    bf16_split(v, hi, lo);
    g_keys_hi[m * 512 + d] = hi;
    g_keys_lo[m * 512 + d] = lo;
    g_keysT_hi[d * 512 + m] = hi;
    g_keysT_lo[d * 512 + m] = lo;
    rs[d] = v; rq[d] = v * v;
    __syncthreads();
    for (int s = 256; s > 0; s >>= 1) {
        if (d < s) { rs[d] += rs[d + s]; rq[d] += rq[d + s]; }
        __syncthreads();
    }
    if (d == 0) { g_sumk[m] = rs[0]; g_k2[m] = rq[0]; }
}

// ---------------- mma.sync GEMM: 128x128 tile, K=512, bf16 hi/lo 4-term ----------------
// mode 0: A=qbf,  B=keys  -> S[n][m] row-major
// mode 1: A=smbf, B=keysT -> upd_q second half (channel-major)
#define OFS_AH 0
#define OFS_AL 16384
#define OFS_BH 32768
#define OFS_BL 49152
#define STAGE  65536

__global__ void __launch_bounds__(256) k_mma_gemm(float* __restrict__ out, int mode) {
    extern __shared__ char smem[];
    uint32_t sb = smem_u32(smem);
    int tid = threadIdx.x;
    int col0 = blockIdx.x * 128;     // output column block (m or d)
    int n0   = blockIdx.y * 128;     // pixel block

    const __nv_bfloat16* Ahi = mode ? g_smbf_hi : g_qbf_hi;
    const __nv_bfloat16* Alo = mode ? g_smbf_lo : g_qbf_lo;
    const __nv_bfloat16* Bhi = mode ? g_keysT_hi : g_keys_hi;
    const __nv_bfloat16* Blo = mode ? g_keysT_lo : g_keys_lo;

    auto load_stage = [&](int buf, int k0) {
        uint32_t base = sb + buf * STAGE;
#pragma unroll
        for (int i = 0; i < 4; i++) {
            int idx = tid + 256 * i;
            int r = idx >> 3, kb = idx & 7;
            uint32_t so = SWZ((uint32_t)(r * 128 + kb * 16));
            const size_t sa = (size_t)(n0 + r) * 512 + k0 + kb * 8;
            const size_t sbx = (size_t)(col0 + r) * 512 + k0 + kb * 8;
            cp16(base + OFS_AH + so, Ahi + sa);
            cp16(base + OFS_AL + so, Alo + sa);
            cp16(base + OFS_BH + so, Bhi + sbx);
            cp16(base + OFS_BL + so, Blo + sbx);
        }
    };

    int lane = tid & 31;
    int wm = (tid >> 5) & 1;          // 2 warps in m
    int wn = (tid >> 5) >> 1;         // 4 warps in n
    int lrow = lane & 15, lhalf = lane >> 4;

    uint32_t arow[4], brow[2];
#pragma unroll
    for (int mf = 0; mf < 4; mf++) arow[mf] = (uint32_t)((wm * 64 + mf * 16 + lrow) * 128 + lhalf * 16);
#pragma unroll
    for (int ng = 0; ng < 2; ng++)  brow[ng] = (uint32_t)((wn * 32 + ng * 16 + lrow) * 128 + lhalf * 16);

    float C[4][4][4];
#pragma unroll
    for (int a = 0; a < 4; a++)
#pragma unroll
        for (int b = 0; b < 4; b++)
#pragma unroll
            for (int c = 0; c < 4; c++) C[a][b][c] = 0.f;

    load_stage(0, 0);   CP_COMMIT();
    load_stage(1, 64);  CP_COMMIT();

#pragma unroll 1
    for (int ch = 0; ch < 8; ch++) {
        if (ch < 7) { CP_WAIT(1); } else { CP_WAIT(0); }
        __syncthreads();
        uint32_t base = sb + (ch & 1) * STAGE;
#pragma unroll
        for (int ks = 0; ks < 4; ks++) {
            uint32_t kofs = (uint32_t)(ks * 32);
            uint32_t ah[4][4], al[4][4];
#pragma unroll
            for (int mf = 0; mf < 4; mf++) {
                uint32_t off = arow[mf] + kofs;
                uint32_t sw = SWZ(off);
                ldsm4(ah[mf], base + OFS_AH + sw);
                ldsm4(al[mf], base + OFS_AL + sw);
            }
            uint32_t bh[2][4], bl[2][4];
#pragma unroll
            for (int ng = 0; ng < 2; ng++) {
                uint32_t off = brow[ng] + kofs;
                uint32_t sw = SWZ(off);
                ldsm4(bh[ng], base + OFS_BH + sw);
                ldsm4(bl[ng], base + OFS_BL + sw);
            }
            // term-major ordering: 16 independent MMAs per pass (no RAW chains)
#pragma unroll
            for (int mf = 0; mf < 4; mf++)
#pragma unroll
                for (int nf = 0; nf < 4; nf++) {
                    int g = nf >> 1, h = nf & 1;
                    mma16816(C[mf][nf], ah[mf], bh[g][h], bh[g][h + 2]);
                }
#pragma unroll
            for (int mf = 0; mf < 4; mf++)
#pragma unroll
                for (int nf = 0; nf < 4; nf++) {
                    int g = nf >> 1, h = nf & 1;
                    mma16816(C[mf][nf], ah[mf], bl[g][h], bl[g][h + 2]);
                }
#pragma unroll
            for (int mf = 0; mf < 4; mf++)
#pragma unroll
                for (int nf = 0; nf < 4; nf++) {
                    int g = nf >> 1, h = nf & 1;
                    mma16816(C[mf][nf], al[mf], bh[g][h], bh[g][h + 2]);
                }
#pragma unroll
            for (int mf = 0; mf < 4; mf++)
#pragma unroll
                for (int nf = 0; nf < 4; nf++) {
                    int g = nf >> 1, h = nf & 1;
                    mma16816(C[mf][nf], al[mf], bl[g][h], bl[g][h + 2]);
                }
        }
        __syncthreads();
        if (ch < 6) { load_stage(ch & 1, (ch + 2) * 64); CP_COMMIT(); }
    }

    // epilogue: frags -> smem [row][132] -> coalesced gmem
    float* fs = (float*)smem;
#pragma unroll
    for (int mf = 0; mf < 4; mf++) {
#pragma unroll
        for (int nf = 0; nf < 4; nf++) {
            int gcol = wn * 32 + (nf >> 1) * 16 + (nf & 1) * 8 + 2 * (lane & 3);
            int grow = wm * 64 + mf * 16 + (lane >> 2);
            *(float2*)&fs[grow * 132 + gcol]       = make_float2(C[mf][nf][0], C[mf][nf][1]);
            *(float2*)&fs[(grow + 8) * 132 + gcol] = make_float2(C[mf][nf][2], C[mf][nf][3]);
        }
    }
    __syncthreads();
    if (mode == 0) {
#pragma unroll 1
        for (int i = 0; i < 64; i++) {
            int idx = i * 256 + tid;
            int row = idx >> 7, col = idx & 127;
            out[(size_t)(n0 + row) * 512 + col0 + col] = fs[row * 132 + col];
        }
    } else {
        int b = n0 >> 12, hw0 = n0 & 4095;
#pragma unroll 1
        for (int i = 0; i < 64; i++) {
            int idx = i * 256 + tid;
            int c = idx >> 7, r = idx & 127;
            out[((size_t)(b * 1024 + 512 + col0 + c)) * 4096 + hw0 + r] = fs[r * 132 + c];
        }
    }
}

// ---------------- row softmax + top2 + column stats (fused) ----------------
__device__ __forceinline__ void merge2(float& m1, int& i1, float& m2, int& i2,
                                       float b1, int bi1, float b2, int bi2) {
    if (b1 > m1 || (b1 == m1 && bi1 < i1)) {
        float om1 = m1; int oi1 = i1;
        m1 = b1; i1 = bi1;
        if (b2 > om1 || (b2 == om1 && bi2 < oi1)) { m2 = b2; i2 = bi2; }
        else { m2 = om1; i2 = oi1; }
    } else {
        if (b1 > m2 || (b1 == m2 && bi1 < i2)) { m2 = b1; i2 = bi1; }
    }
}

__global__ void k_rowsm(const float* __restrict__ S, float* __restrict__ SM) {
    __shared__ float cbuf[8][512];
    int warp = threadIdx.x >> 5, lane = threadIdx.x & 31;
    int n = blockIdx.x * 8 + warp;
    const float* row = S + (size_t)n * MM;

    float v[16];
    float m1 = -FLT_MAX, m2 = -FLT_MAX;
    int i1 = 0x7fffffff, i2 = 0x7fffffff;
#pragma unroll
    for (int j = 0; j < 16; j++) {
        float val = row[lane + 32 * j];
        v[j] = val;
        int idx = lane + 32 * j;
        if (val > m1 || (val == m1 && idx < i1)) { m2 = m1; i2 = i1; m1 = val; i1 = idx; }
        else if (val > m2 || (val == m2 && idx < i2)) { m2 = val; i2 = idx; }
    }
#pragma unroll
    for (int off = 16; off; off >>= 1) {
        float b1 = __shfl_xor_sync(0xffffffffu, m1, off);
        int  bi1 = __shfl_xor_sync(0xffffffffu, i1, off);
        float b2 = __shfl_xor_sync(0xffffffffu, m2, off);
        int  bi2 = __shfl_xor_sync(0xffffffffu, i2, off);
        merge2(m1, i1, m2, i2, b1, bi1, b2, bi2);
    }
    float rmax = m1;
    float s = 0.f;
#pragma unroll
    for (int j = 0; j < 16; j++) {
        v[j] = expf(v[j] - rmax);
        s += v[j];
    }
#pragma unroll
    for (int off = 16; off; off >>= 1) s += __shfl_xor_sync(0xffffffffu, s, off);
    float inv = 1.0f / s;
    float rme = expf(rmax);           // |score| <= ~25, safe in f32
    float* orow = SM + (size_t)n * MM;
#pragma unroll
    for (int j = 0; j < 16; j++) {
        float p = v[j] * inv;
        orow[lane + 32 * j] = p;
        __nv_bfloat16 hi, lo;
        bf16_split(p, hi, lo);
        g_smbf_hi[(size_t)n * 512 + lane + 32 * j] = hi;
        g_smbf_lo[(size_t)n * 512 + lane + 32 * j] = lo;
        cbuf[warp][lane + 32 * j] = v[j] * rme;   // = exp(s[n,m])
    }
    if (lane == 0) {
        g_top1[n] = i1; g_top2[n] = i2;
        g_m1[n] = m1;   g_m2[n] = m2;
    }
    __syncthreads();
    // column partials over this block's 8 rows
    for (int c = threadIdx.x; c < 512; c += 256) {
        float cs = 0.f, cm = 0.f;
#pragma unroll
        for (int r = 0; r < 8; r++) {
            float x = cbuf[r][c];
            cs += x;
            cm = fmaxf(cm, x);
        }
        atomicAdd(&g_colsum[c], cs);
        atomicMax((int*)&g_cmx[c], __float_as_int(cm));   // positive floats: int-compare valid
    }
}

__global__ void k_colfin() {
    int c = threadIdx.x;
    g_colinv[c] = 1.0f / g_colsum[c];
}

// ---------------- per-pixel stats: wgt + compactness/separateness (analytic) ----------------
__global__ void k_pixstats() {
    int n = blockIdx.x * 256 + threadIdx.x;
    int g1 = g_top1[n], g2 = g_top2[n];
    float m1 = g_m1[n], m2 = g_m2[n];
    float sumq = g_sumq[n];

    g_wgt[n] = expf(m1) / g_cmx[g1];

    float cpos = 1.0f + g_k2[g1] - 2.0f * m1;               // ||q-kp||^2
    float cneg = 1.0f + g_k2[g2] - 2.0f * m2;               // ||q-kn||^2
    const float eps = 1e-6f;
    float dpos = sqrtf(fmaxf(cpos + 2.0f * eps * (sumq - g_sumk[g1]) + 512.0f * eps * eps, 0.f));
    float dneg = sqrtf(fmaxf(cneg + 2.0f * eps * (sumq - g_sumk[g2]) + 512.0f * eps * eps, 0.f));
    float hinge = fmaxf(dpos - dneg + 1.0f, 0.f);

    __shared__ float sc[256], sh[256];
    int t = threadIdx.x;
    sc[t] = cpos; sh[t] = hinge;
    __syncthreads();
    for (int s = 128; s > 0; s >>= 1) {
        if (t < s) { sc[t] += sc[t + s]; sh[t] += sh[t + s]; }
        __syncthreads();
    }
    if (t == 0) {
        atomicAdd(&g_acc[0], sc[0]);
        atomicAdd(&g_acc[1], sh[0]);
    }
}

// in-place transform raw scores -> s_query (no max-shift needed: exp(s) <= ~e^25)
__global__ void k_sq(float* __restrict__ S) {
    long long idx = (long long)blockIdx.x * blockDim.x + threadIdx.x;
    int m = (int)(idx & 511);
    S[idx] = expf(S[idx]) * g_colinv[m];
}

// ---------------- segment sum (vector reductions) ----------------
__global__ void k_scatter(const float* __restrict__ qn) {
    int n = blockIdx.x * 256 + threadIdx.x;
    int b = n >> 12, hw = n & 4095;
    int g = g_top1[n];
    float w = g_wgt[n];
    const float* qp = qn + (size_t)b * 1024 * HW + hw;
    float* dst = g_qupd + (size_t)g * DD;
#pragma unroll 2
    for (int d = 0; d < DD; d += 4) {
        float a0 = w * qp[(size_t)(d + 0) * HW];
        float a1 = w * qp[(size_t)(d + 1) * HW];
        float a2 = w * qp[(size_t)(d + 2) * HW];
        float a3 = w * qp[(size_t)(d + 3) * HW];
        red_v4(dst + d, a0, a1, a2, a3);
    }
}

__global__ void k_updmem(const float* __restrict__ keys, float* __restrict__ out) {
    int m = blockIdx.x, t = threadIdx.x;
    float u[4];
    float s = 0.f;
#pragma unroll
    for (int r = 0; r < 4; r++) {
        int d = t + 128 * r;
        float x = g_qupd[(size_t)m * DD + d] + keys[(size_t)m * DD + d];
        u[r] = x;
        s += x * x;
    }
    __shared__ float red[128];
    red[t] = s;
    __syncthreads();
    for (int k = 64; k > 0; k >>= 1) {
        if (t < k) red[t] += red[t + k];
        __syncthreads();
    }
    float inv = 1.0f / fmaxf(sqrtf(red[0]), 1e-12f);
#pragma unroll
    for (int r = 0; r < 4; r++) {
        int d = t + 128 * r;
        out[OFF_UPDMEM + (size_t)m * DD + d] = u[r] * inv;
    }
}

__global__ void k_fin(float* __restrict__ out) {
    if (threadIdx.x == 0) {
        out[OFF_COMP] = (float)((double)g_acc[0] / ((double)NPIX * (double)DD));
        out[OFF_SEP]  = (float)((double)g_acc[1] / (double)NPIX);
    }
}

// ---------------- launch ----------------
#define GEMM_SMEM 131072

extern "C" void kernel_launch(void* const* d_in, const int* in_sizes, int n_in,
                              void* d_out, int out_size) {
    const float* query = (const float*)d_in[0];
    const float* keys  = (const float*)d_in[1];
    float* out  = (float*)d_out;
    float* updq = out + OFF_UPDQ;
    float* sq   = out + OFF_SQ;   // raw scores until k_sq transforms them
    float* sm   = out + OFF_SM;

    cudaFuncSetAttribute(k_mma_gemm, cudaFuncAttributeMaxDynamicSharedMemorySize, GEMM_SMEM);

    k_init<<<(MM * DD) / 256, 256>>>();
    k_norm<<<NPIX / 256, 256>>>(query);
    k_prep_q<<<dim3(HW / 32, DD / 32, BB), 256>>>(query, updq);
    k_prep_keys<<<MM, DD>>>(keys);

    // GEMM1: raw scores S[n][m]
    k_mma_gemm<<<dim3(MM / 128, NPIX / 128), 256, GEMM_SMEM>>>(sq, 0);

    // fused row softmax + top2 + column stats
    k_rowsm<<<NPIX / 8, 256>>>(sq, sm);
    k_colfin<<<1, 512>>>();

    k_pixstats<<<NPIX / 256, 256>>>();
    k_scatter<<<NPIX / 256, 256>>>(updq);
    k_sq<<<(int)(((long long)NPIX * MM) / 256), 256>>>(sq);

    // GEMM2: concat_mem -> upd_q second half
    k_mma_gemm<<<dim3(DD / 128, NPIX / 128), 256, GEMM_SMEM>>>(updq, 1);

    k_updmem<<<MM, 128>>>(keys, out);
    k_fin<<<1, 32>>>(out);
}

// round 12
// speedup vs baseline: 2.0849x; 1.0234x over previous
#include <cuda_runtime.h>
#include <cuda_bf16.h>
#include <math.h>
#include <float.h>
#include <stdint.h>

// Problem constants
#define NPIX 65536      // B*H*W
#define BB   16
#define DD   512
#define HW   4096
#define MM   512

// Output offsets (floats), tuple order: upd_q, upd_mem, s_query, s_memory, separateness, compactness
#define OFF_UPDQ   ((size_t)0)
#define OFF_UPDMEM ((size_t)67108864)
#define OFF_SQ     ((size_t)67371008)
#define OFF_SM     ((size_t)100925440)
#define OFF_SEP    ((size_t)134479872)
#define OFF_COMP   ((size_t)134479873)

// ---------------- scratch (static device memory) ----------------
__device__ float g_m2[NPIX];          // approx 2nd max (threshold for refine)
__device__ int   g_top1[NPIX];
__device__ int   g_top2[NPIX];
__device__ float g_e1[NPIX];          // exact dot q.k_top1
__device__ float g_e2[NPIX];          // exact dot q.k_top2
__device__ float g_s1g[NPIX];         // GEMM score at refined top1 (for wgt)
__device__ float g_q2[NPIX];          // exact ||qn||^2
__device__ float g_sumq[NPIX];        // exact sum(qn)
__device__ float g_wgt[NPIX];
__device__ float g_colsum[MM];
__device__ float g_cmx[MM];           // per-column max of exp(s)
__device__ float g_colinv[MM];
__device__ float g_sumk[MM];
__device__ float g_k2[MM];
__device__ float g_acc[2];            // 0: compactness sum, 1: separateness sum
__device__ __align__(16) float g_qupd[MM * DD];

// bf16 hi/lo operands for tensor-core GEMMs (all [row][512] K-major)
__device__ __nv_bfloat16 g_qbf_hi[(size_t)NPIX * DD];
__device__ __nv_bfloat16 g_qbf_lo[(size_t)NPIX * DD];
__device__ __nv_bfloat16 g_smbf_hi[(size_t)NPIX * MM];
__device__ __nv_bfloat16 g_smbf_lo[(size_t)NPIX * MM];
__device__ __nv_bfloat16 g_keys_hi[MM * DD];
__device__ __nv_bfloat16 g_keys_lo[MM * DD];
__device__ __nv_bfloat16 g_keysT_hi[DD * MM];
__device__ __nv_bfloat16 g_keysT_lo[DD * MM];

// ---------------- helpers ----------------
__device__ __forceinline__ uint32_t smem_u32(const void* p) {
    uint32_t a;
    asm("{ .reg .u64 t; cvta.to.shared.u64 t, %1; cvt.u32.u64 %0, t; }" : "=r"(a) : "l"(p));
    return a;
}
#define SWZ(x) ((x) ^ (((x) >> 3) & 0x70))

__device__ __forceinline__ void cp16(uint32_t dst, const void* src) {
    asm volatile("cp.async.cg.shared.global [%0], [%1], 16;"
                 :: "r"(dst), "l"(__cvta_generic_to_global(src)));
}
#define CP_COMMIT() asm volatile("cp.async.commit_group;" ::: "memory")
#define CP_WAIT(n)  asm volatile("cp.async.wait_group %0;" :: "n"(n) : "memory")

__device__ __forceinline__ void ldsm4(uint32_t* r, uint32_t addr) {
    asm volatile("ldmatrix.sync.aligned.m8n8.x4.shared.b16 {%0,%1,%2,%3}, [%4];"
                 : "=r"(r[0]), "=r"(r[1]), "=r"(r[2]), "=r"(r[3]) : "r"(addr));
}
__device__ __forceinline__ void mma16816(float* c, const uint32_t* a, uint32_t b0, uint32_t b1) {
    asm volatile("mma.sync.aligned.m16n8k16.row.col.f32.bf16.bf16.f32 "
                 "{%0,%1,%2,%3}, {%4,%5,%6,%7}, {%8,%9}, {%0,%1,%2,%3};"
                 : "+f"(c[0]), "+f"(c[1]), "+f"(c[2]), "+f"(c[3])
                 : "r"(a[0]), "r"(a[1]), "r"(a[2]), "r"(a[3]), "r"(b0), "r"(b1));
}
__device__ __forceinline__ void red_v4(float* dst, float a, float b, float c, float d) {
    asm volatile("red.global.add.v4.f32 [%0], {%1,%2,%3,%4};"
                 :: "l"(__cvta_generic_to_global(dst)), "f"(a), "f"(b), "f"(c), "f"(d) : "memory");
}

__device__ __forceinline__ void bf16_split(float v, __nv_bfloat16& hi, __nv_bfloat16& lo) {
    hi = __float2bfloat16(v);
    lo = __float2bfloat16(v - __bfloat162float(hi));
}

// ---------------- init (graph-replay safe zeroing) ----------------
__global__ void k_init() {
    int i = blockIdx.x * 256 + threadIdx.x;
    g_qupd[i] = 0.f;
    if (i < MM) { g_colsum[i] = 0.f; g_cmx[i] = 0.f; }
    if (i < 2) g_acc[i] = 0.f;
}

// ---------------- fused normalize + layout prep ----------------
// One block = 32 pixels (hw tile) x all 512 channels of one batch.
// Produces: updq first half (channel-major f32) + qbf hi/lo ([n][d] bf16).
__global__ void k_prep(const float* __restrict__ q, float* __restrict__ updq) {
    extern __shared__ float sp[];              // [512][33]
    float* red    = sp + 512 * 33;             // [8][32]
    float* invrow = red + 256;                 // [32]
    int b = blockIdx.y, hw0 = blockIdx.x * 32;
    int tx = threadIdx.x & 31, ty = threadIdx.x >> 5;

    const float* base = q + (size_t)b * 512 * 4096 + hw0 + tx;
    float s2 = 0.f;
#pragma unroll 8
    for (int i = 0; i < 64; i++) {
        int d = ty + 8 * i;
        float v = base[(size_t)d * 4096];
        sp[d * 33 + tx] = v;
        s2 += v * v;
    }
    red[ty * 32 + tx] = s2;
    __syncthreads();
    if (ty == 0) {
        float t = 0.f;
#pragma unroll
        for (int r = 0; r < 8; r++) t += red[r * 32 + tx];
        invrow[tx] = 1.0f / fmaxf(sqrtf(t), 1e-12f);
    }
    __syncthreads();
    float inv = invrow[tx];
    float* ubase = updq + (size_t)b * 1024 * 4096 + hw0 + tx;
#pragma unroll 8
    for (int i = 0; i < 64; i++) {
        int d = ty + 8 * i;
        float x = sp[d * 33 + tx] * inv;
        sp[d * 33 + tx] = x;
        ubase[(size_t)d * 4096] = x;
    }
    __syncthreads();
    // transposed bf16 hi/lo writes: [n][d] contiguous
#pragma unroll 4
    for (int i = 0; i < 32; i++) {
        int idx = threadIdx.x + 256 * i;       // (n:32) x (dpair:256)
        int nl = idx >> 8, dp = idx & 255;
        float x0 = sp[(2 * dp) * 33 + nl];
        float x1 = sp[(2 * dp + 1) * 33 + nl];
        __nv_bfloat16 h0, l0, h1, l1;
        bf16_split(x0, h0, l0);
        bf16_split(x1, h1, l1);
        size_t off = ((size_t)((b << 12) + hw0 + nl)) * 512 + 2 * dp;
        __nv_bfloat162 ph; ph.x = h0; ph.y = h1;
        __nv_bfloat162 pl; pl.x = l0; pl.y = l1;
        *(__nv_bfloat162*)(g_qbf_hi + off) = ph;
        *(__nv_bfloat162*)(g_qbf_lo + off) = pl;
    }
}

// keys -> bf16 hi/lo [m][d] + transposed [d][m] + per-key sum / norm^2
__global__ void k_prep_keys(const float* __restrict__ keys) {
    __shared__ float rs[512], rq[512];
    int m = blockIdx.x, d = threadIdx.x;
    float v = keys[m * 512 + d];
    __nv_bfloat16 hi, lo;
    bf16_split(v, hi, lo);
    g_keys_hi[m * 512 + d] = hi;
    g_keys_lo[m * 512 + d] = lo;
    g_keysT_hi[d * 512 + m] = hi;
    g_keysT_lo[d * 512 + m] = lo;
    rs[d] = v; rq[d] = v * v;
    __syncthreads();
    for (int s = 256; s > 0; s >>= 1) {
        if (d < s) { rs[d] += rs[d + s]; rq[d] += rq[d + s]; }
        __syncthreads();
    }
    if (d == 0) { g_sumk[m] = rs[0]; g_k2[m] = rq[0]; }
}

// ---------------- mma.sync GEMM: 128x128 tile, K=512, bf16 hi/lo 3-term ----------------
#define OFS_AH 0
#define OFS_AL 16384
#define OFS_BH 32768
#define OFS_BL 49152
#define STAGE  65536

__global__ void __launch_bounds__(256) k_mma_gemm(float* __restrict__ out, int mode) {
    extern __shared__ char smem[];
    uint32_t sb = smem_u32(smem);
    int tid = threadIdx.x;
    int col0 = blockIdx.x * 128;
    int n0   = blockIdx.y * 128;

    const __nv_bfloat16* Ahi = mode ? g_smbf_hi : g_qbf_hi;
    const __nv_bfloat16* Alo = mode ? g_smbf_lo : g_qbf_lo;
    const __nv_bfloat16* Bhi = mode ? g_keysT_hi : g_keys_hi;
    const __nv_bfloat16* Blo = mode ? g_keysT_lo : g_keys_lo;

    auto load_stage = [&](int buf, int k0) {
        uint32_t base = sb + buf * STAGE;
#pragma unroll
        for (int i = 0; i < 4; i++) {
            int idx = tid + 256 * i;
            int r = idx >> 3, kb = idx & 7;
            uint32_t so = SWZ((uint32_t)(r * 128 + kb * 16));
            const size_t sa = (size_t)(n0 + r) * 512 + k0 + kb * 8;
            const size_t sbx = (size_t)(col0 + r) * 512 + k0 + kb * 8;
            cp16(base + OFS_AH + so, Ahi + sa);
            cp16(base + OFS_AL + so, Alo + sa);
            cp16(base + OFS_BH + so, Bhi + sbx);
            cp16(base + OFS_BL + so, Blo + sbx);
        }
    };

    int lane = tid & 31;
    int wm = (tid >> 5) & 1;
    int wn = (tid >> 5) >> 1;
    int lrow = lane & 15, lhalf = lane >> 4;

    uint32_t arow[4], brow[2];
#pragma unroll
    for (int mf = 0; mf < 4; mf++) arow[mf] = (uint32_t)((wm * 64 + mf * 16 + lrow) * 128 + lhalf * 16);
#pragma unroll
    for (int ng = 0; ng < 2; ng++)  brow[ng] = (uint32_t)((wn * 32 + ng * 16 + lrow) * 128 + lhalf * 16);

    float C[4][4][4];
#pragma unroll
    for (int a = 0; a < 4; a++)
#pragma unroll
        for (int b = 0; b < 4; b++)
#pragma unroll
            for (int c = 0; c < 4; c++) C[a][b][c] = 0.f;

    load_stage(0, 0);   CP_COMMIT();
    load_stage(1, 64);  CP_COMMIT();

#pragma unroll 1
    for (int ch = 0; ch < 8; ch++) {
        if (ch < 7) { CP_WAIT(1); } else { CP_WAIT(0); }
        __syncthreads();
        uint32_t base = sb + (ch & 1) * STAGE;
#pragma unroll
        for (int ks = 0; ks < 4; ks++) {
            uint32_t kofs = (uint32_t)(ks * 32);
            uint32_t ah[4][4], al[4][4];
#pragma unroll
            for (int mf = 0; mf < 4; mf++) {
                uint32_t off = arow[mf] + kofs;
                uint32_t sw = SWZ(off);
                ldsm4(ah[mf], base + OFS_AH + sw);
                ldsm4(al[mf], base + OFS_AL + sw);
            }
            uint32_t bh[2][4], bl[2][4];
#pragma unroll
            for (int ng = 0; ng < 2; ng++) {
                uint32_t off = brow[ng] + kofs;
                uint32_t sw = SWZ(off);
                ldsm4(bh[ng], base + OFS_BH + sw);
                ldsm4(bl[ng], base + OFS_BL + sw);
            }
            // term-major ordering, 3 terms (hh, hl, lh)
#pragma unroll
            for (int mf = 0; mf < 4; mf++)
#pragma unroll
                for (int nf = 0; nf < 4; nf++) {
                    int g = nf >> 1, h = nf & 1;
                    mma16816(C[mf][nf], ah[mf], bh[g][h], bh[g][h + 2]);
                }
#pragma unroll
            for (int mf = 0; mf < 4; mf++)
#pragma unroll
                for (int nf = 0; nf < 4; nf++) {
                    int g = nf >> 1, h = nf & 1;
                    mma16816(C[mf][nf], ah[mf], bl[g][h], bl[g][h + 2]);
                }
#pragma unroll
            for (int mf = 0; mf < 4; mf++)
#pragma unroll
                for (int nf = 0; nf < 4; nf++) {
                    int g = nf >> 1, h = nf & 1;
                    mma16816(C[mf][nf], al[mf], bh[g][h], bh[g][h + 2]);
                }
        }
        __syncthreads();
        if (ch < 6) { load_stage(ch & 1, (ch + 2) * 64); CP_COMMIT(); }
    }

    // epilogue: frags -> smem [row][132] -> coalesced gmem
    float* fs = (float*)smem;
#pragma unroll
    for (int mf = 0; mf < 4; mf++) {
#pragma unroll
        for (int nf = 0; nf < 4; nf++) {
            int gcol = wn * 32 + (nf >> 1) * 16 + (nf & 1) * 8 + 2 * (lane & 3);
            int grow = wm * 64 + mf * 16 + (lane >> 2);
            *(float2*)&fs[grow * 132 + gcol]       = make_float2(C[mf][nf][0], C[mf][nf][1]);
            *(float2*)&fs[(grow + 8) * 132 + gcol] = make_float2(C[mf][nf][2], C[mf][nf][3]);
        }
    }
    __syncthreads();
    if (mode == 0) {
#pragma unroll 1
        for (int i = 0; i < 64; i++) {
            int idx = i * 256 + tid;
            int row = idx >> 7, col = idx & 127;
            out[(size_t)(n0 + row) * 512 + col0 + col] = fs[row * 132 + col];
        }
    } else {
        int b = n0 >> 12, hw0 = n0 & 4095;
#pragma unroll 1
        for (int i = 0; i < 64; i++) {
            int idx = i * 256 + tid;
            int c = idx >> 7, r = idx & 127;
            out[((size_t)(b * 1024 + 512 + col0 + c)) * 4096 + hw0 + r] = fs[r * 132 + c];
        }
    }
}

// ---------------- row softmax + approx top2 + column stats (fused) ----------------
__device__ __forceinline__ void merge2(float& m1, int& i1, float& m2, int& i2,
                                       float b1, int bi1, float b2, int bi2) {
    if (b1 > m1 || (b1 == m1 && bi1 < i1)) {
        float om1 = m1; int oi1 = i1;
        m1 = b1; i1 = bi1;
        if (b2 > om1 || (b2 == om1 && bi2 < oi1)) { m2 = b2; i2 = bi2; }
        else { m2 = om1; i2 = oi1; }
    } else {
        if (b1 > m2 || (b1 == m2 && bi1 < i2)) { m2 = b1; i2 = bi1; }
    }
}

__global__ void k_rowsm(const float* __restrict__ S, float* __restrict__ SM) {
    __shared__ float cbuf[8][512];
    int warp = threadIdx.x >> 5, lane = threadIdx.x & 31;
    int n = blockIdx.x * 8 + warp;
    const float* row = S + (size_t)n * MM;

    float v[16];
    float m1 = -FLT_MAX, m2 = -FLT_MAX;
    int i1 = 0x7fffffff, i2 = 0x7fffffff;
#pragma unroll
    for (int j = 0; j < 16; j++) {
        float val = row[lane + 32 * j];
        v[j] = val;
        int idx = lane + 32 * j;
        if (val > m1 || (val == m1 && idx < i1)) { m2 = m1; i2 = i1; m1 = val; i1 = idx; }
        else if (val > m2 || (val == m2 && idx < i2)) { m2 = val; i2 = idx; }
    }
#pragma unroll
    for (int off = 16; off; off >>= 1) {
        float b1 = __shfl_xor_sync(0xffffffffu, m1, off);
        int  bi1 = __shfl_xor_sync(0xffffffffu, i1, off);
        float b2 = __shfl_xor_sync(0xffffffffu, m2, off);
        int  bi2 = __shfl_xor_sync(0xffffffffu, i2, off);
        merge2(m1, i1, m2, i2, b1, bi1, b2, bi2);
    }
    float rmax = m1;
    float s = 0.f;
#pragma unroll
    for (int j = 0; j < 16; j++) {
        v[j] = expf(v[j] - rmax);
        s += v[j];
    }
#pragma unroll
    for (int off = 16; off; off >>= 1) s += __shfl_xor_sync(0xffffffffu, s, off);
    float inv = 1.0f / s;
    float rme = expf(rmax);           // |score| <= ~23, safe in f32
    float* orow = SM + (size_t)n * MM;
#pragma unroll
    for (int j = 0; j < 16; j++) {
        float p = v[j] * inv;
        orow[lane + 32 * j] = p;
        __nv_bfloat16 hi, lo;
        bf16_split(p, hi, lo);
        g_smbf_hi[(size_t)n * 512 + lane + 32 * j] = hi;
        g_smbf_lo[(size_t)n * 512 + lane + 32 * j] = lo;
        cbuf[warp][lane + 32 * j] = v[j] * rme;   // = exp(s[n,m])
    }
    if (lane == 0) g_m2[n] = m2;
    __syncthreads();
    for (int c = threadIdx.x; c < 512; c += 256) {
        float cs = 0.f, cm = 0.f;
#pragma unroll
        for (int r = 0; r < 8; r++) {
            float x = cbuf[r][c];
            cs += x;
            cm = fmaxf(cm, x);
        }
        atomicAdd(&g_colsum[c], cs);
        atomicMax((int*)&g_cmx[c], __float_as_int(cm));   // positive floats: int-compare valid
    }
}

__global__ void k_colfin() {
    int c = threadIdx.x;
    g_colinv[c] = 1.0f / g_colsum[c];
}

// ---------------- exact top-2 refinement (flip-proof) ----------------
// One warp per pixel: rescan score row for candidates >= m2_approx - 1e-3,
// recompute their dots EXACTLY (f32, from hi+lo bf16 = exact qn), pick exact top-2.
__global__ void k_refine(const float* __restrict__ S, const float* __restrict__ keys) {
    int warp = threadIdx.x >> 5, lane = threadIdx.x & 31;
    int n = blockIdx.x * 8 + warp;

    // exact qn in registers (hi+lo reconstruction is exact)
    float qv[16];
    {
        const __nv_bfloat16* qh = g_qbf_hi + (size_t)n * 512 + lane * 16;
        const __nv_bfloat16* ql = g_qbf_lo + (size_t)n * 512 + lane * 16;
#pragma unroll
        for (int i = 0; i < 16; i++)
            qv[i] = __bfloat162float(qh[i]) + __bfloat162float(ql[i]);
    }
    float sq = 0.f, q2 = 0.f;
#pragma unroll
    for (int i = 0; i < 16; i++) { sq += qv[i]; q2 += qv[i] * qv[i]; }
#pragma unroll
    for (int off = 16; off; off >>= 1) {
        sq += __shfl_xor_sync(0xffffffffu, sq, off);
        q2 += __shfl_xor_sync(0xffffffffu, q2, off);
    }

    const float* row = S + (size_t)n * MM;
    float thr = g_m2[n] - 1e-3f;
    float e1 = -FLT_MAX, e2 = -FLT_MAX, s1g = 0.f, s2g = 0.f;
    int i1 = 0x7fffffff, i2 = 0x7fffffff;
#pragma unroll 1
    for (int j = 0; j < 16; j++) {
        float val = row[lane + 32 * j];
        unsigned mask = __ballot_sync(0xffffffffu, val >= thr);
        while (mask) {
            int src = __ffs(mask) - 1;
            mask &= mask - 1;
            int m = src + 32 * j;
            float gs = __shfl_sync(0xffffffffu, val, src);
            // exact f32 dot
            float d = 0.f;
            const float* kp = keys + (size_t)m * 512 + lane * 16;
#pragma unroll
            for (int i = 0; i < 16; i++) d += qv[i] * kp[i];
#pragma unroll
            for (int off = 16; off; off >>= 1) d += __shfl_xor_sync(0xffffffffu, d, off);
            if (d > e1 || (d == e1 && m < i1)) {
                e2 = e1; i2 = i1; s2g = s1g;
                e1 = d; i1 = m; s1g = gs;
            } else if (d > e2 || (d == e2 && m < i2)) {
                e2 = d; i2 = m; s2g = gs;
            }
        }
    }
    if (lane == 0) {
        g_top1[n] = i1; g_top2[n] = i2;
        g_e1[n] = e1;   g_e2[n] = e2;
        g_s1g[n] = s1g;
        g_q2[n] = q2;   g_sumq[n] = sq;
    }
}

// ---------------- per-pixel stats: wgt + compactness/separateness (analytic, exact dots) ----------------
__global__ void k_pixstats() {
    int n = blockIdx.x * 256 + threadIdx.x;
    int g1 = g_top1[n], g2 = g_top2[n];
    float e1 = g_e1[n], e2 = g_e2[n];
    float q2 = g_q2[n], sumq = g_sumq[n];

    g_wgt[n] = expf(g_s1g[n]) / g_cmx[g1];

    float cpos = q2 + g_k2[g1] - 2.0f * e1;
    float cneg = q2 + g_k2[g2] - 2.0f * e2;
    const float eps = 1e-6f;
    float dpos = sqrtf(fmaxf(cpos + 2.0f * eps * (sumq - g_sumk[g1]) + 512.0f * eps * eps, 0.f));
    float dneg = sqrtf(fmaxf(cneg + 2.0f * eps * (sumq - g_sumk[g2]) + 512.0f * eps * eps, 0.f));
    float hinge = fmaxf(dpos - dneg + 1.0f, 0.f);

    __shared__ float sc[256], sh[256];
    int t = threadIdx.x;
    sc[t] = cpos; sh[t] = hinge;
    __syncthreads();
    for (int s = 128; s > 0; s >>= 1) {
        if (t < s) { sc[t] += sc[t + s]; sh[t] += sh[t + s]; }
        __syncthreads();
    }
    if (t == 0) {
        atomicAdd(&g_acc[0], sc[0]);
        atomicAdd(&g_acc[1], sh[0]);
    }
}

// in-place transform raw scores -> s_query (|score| <= ~23 so exp is safe unshifted)
__global__ void k_sq(float* __restrict__ S) {
    long long idx = (long long)blockIdx.x * blockDim.x + threadIdx.x;
    int m = (int)(idx & 511);
    S[idx] = expf(S[idx]) * g_colinv[m];
}

// ---------------- segment sum (vector reductions) ----------------
__global__ void k_scatter(const float* __restrict__ qn) {
    int n = blockIdx.x * 256 + threadIdx.x;
    int b = n >> 12, hw = n & 4095;
    int g = g_top1[n];
    float w = g_wgt[n];
    const float* qp = qn + (size_t)b * 1024 * HW + hw;
    float* dst = g_qupd + (size_t)g * DD;
#pragma unroll 2
    for (int d = 0; d < DD; d += 4) {
        float a0 = w * qp[(size_t)(d + 0) * HW];
        float a1 = w * qp[(size_t)(d + 1) * HW];
        float a2 = w * qp[(size_t)(d + 2) * HW];
        float a3 = w * qp[(size_t)(d + 3) * HW];
        red_v4(dst + d, a0, a1, a2, a3);
    }
}

__global__ void k_updmem(const float* __restrict__ keys, float* __restrict__ out) {
    int m = blockIdx.x, t = threadIdx.x;
    float u[4];
    float s = 0.f;
#pragma unroll
    for (int r = 0; r < 4; r++) {
        int d = t + 128 * r;
        float x = g_qupd[(size_t)m * DD + d] + keys[(size_t)m * DD + d];
        u[r] = x;
        s += x * x;
    }
    __shared__ float red[128];
    red[t] = s;
    __syncthreads();
    for (int k = 64; k > 0; k >>= 1) {
        if (t < k) red[t] += red[t + k];
        __syncthreads();
    }
    float inv = 1.0f / fmaxf(sqrtf(red[0]), 1e-12f);
#pragma unroll
    for (int r = 0; r < 4; r++) {
        int d = t + 128 * r;
        out[OFF_UPDMEM + (size_t)m * DD + d] = u[r] * inv;
    }
}

__global__ void k_fin(float* __restrict__ out) {
    if (threadIdx.x == 0) {
        out[OFF_COMP] = (float)((double)g_acc[0] / ((double)NPIX * (double)DD));
        out[OFF_SEP]  = (float)((double)g_acc[1] / (double)NPIX);
    }
}

// ---------------- launch ----------------
#define GEMM_SMEM 131072
#define PREP_SMEM (512 * 33 * 4 + 256 * 4 + 32 * 4)

extern "C" void kernel_launch(void* const* d_in, const int* in_sizes, int n_in,
                              void* d_out, int out_size) {
    const float* query = (const float*)d_in[0];
    const float* keys  = (const float*)d_in[1];
    float* out  = (float*)d_out;
    float* updq = out + OFF_UPDQ;
    float* sq   = out + OFF_SQ;   // raw scores until k_sq transforms them
    float* sm   = out + OFF_SM;

    cudaFuncSetAttribute(k_mma_gemm, cudaFuncAttributeMaxDynamicSharedMemorySize, GEMM_SMEM);
    cudaFuncSetAttribute(k_prep, cudaFuncAttributeMaxDynamicSharedMemorySize, PREP_SMEM);

    k_init<<<(MM * DD) / 256, 256>>>();
    k_prep<<<dim3(HW / 32, BB), 256, PREP_SMEM>>>(query, updq);
    k_prep_keys<<<MM, DD>>>(keys);

    // GEMM1: raw scores S[n][m]
    k_mma_gemm<<<dim3(MM / 128, NPIX / 128), 256, GEMM_SMEM>>>(sq, 0);

    // fused row softmax + column stats
    k_rowsm<<<NPIX / 8, 256>>>(sq, sm);
    k_colfin<<<1, 512>>>();

    // exact top-2 + per-pixel stats
    k_refine<<<NPIX / 8, 256>>>(sq, keys);
    k_pixstats<<<NPIX / 256, 256>>>();
    k_scatter<<<NPIX / 256, 256>>>(updq);
    k_sq<<<(int)(((long long)NPIX * MM) / 256), 256>>>(sq);

    // GEMM2: concat_mem -> upd_q second half
    k_mma_gemm<<<dim3(DD / 128, NPIX / 128), 256, GEMM_SMEM>>>(updq, 1);

    k_updmem<<<MM, 128>>>(keys, out);
    k_fin<<<1, 32>>>(out);
}

// round 13
// speedup vs baseline: 2.1945x; 1.0525x over previous
#include <cuda_runtime.h>
#include <cuda_bf16.h>
#include <math.h>
#include <float.h>
#include <stdint.h>

// Problem constants
#define NPIX 65536      // B*H*W
#define BB   16
#define DD   512
#define HW   4096
#define MM   512

// Output offsets (floats), tuple order: upd_q, upd_mem, s_query, s_memory, separateness, compactness
#define OFF_UPDQ   ((size_t)0)
#define OFF_UPDMEM ((size_t)67108864)
#define OFF_SQ     ((size_t)67371008)
#define OFF_SM     ((size_t)100925440)
#define OFF_SEP    ((size_t)134479872)
#define OFF_COMP   ((size_t)134479873)

// ---------------- scratch (static device memory) ----------------
__device__ int   g_top1[NPIX];
__device__ int   g_top2[NPIX];
__device__ float g_e1[NPIX];          // exact dot q.k_top1
__device__ float g_e2[NPIX];          // exact dot q.k_top2
__device__ float g_s1g[NPIX];         // GEMM score at refined top1 (for wgt)
__device__ float g_q2[NPIX];          // exact ||qn||^2
__device__ float g_sumq[NPIX];        // exact sum(qn)
__device__ float g_wgt[NPIX];
__device__ float g_colsum[MM];
__device__ float g_cmx[MM];           // per-column max of exp(s)
__device__ float g_colinv[MM];
__device__ float g_sumk[MM];
__device__ float g_k2[MM];
__device__ float g_acc[2];            // 0: compactness sum, 1: separateness sum
__device__ __align__(16) float g_qupd[MM * DD];

// bf16 hi/lo operands for tensor-core GEMMs (all [row][512] K-major)
__device__ __nv_bfloat16 g_qbf_hi[(size_t)NPIX * DD];
__device__ __nv_bfloat16 g_qbf_lo[(size_t)NPIX * DD];
__device__ __nv_bfloat16 g_smbf_hi[(size_t)NPIX * MM];
__device__ __nv_bfloat16 g_smbf_lo[(size_t)NPIX * MM];
__device__ __nv_bfloat16 g_keys_hi[MM * DD];
__device__ __nv_bfloat16 g_keys_lo[MM * DD];
__device__ __nv_bfloat16 g_keysT_hi[DD * MM];
__device__ __nv_bfloat16 g_keysT_lo[DD * MM];

// ---------------- helpers ----------------
__device__ __forceinline__ uint32_t smem_u32(const void* p) {
    uint32_t a;
    asm("{ .reg .u64 t; cvta.to.shared.u64 t, %1; cvt.u32.u64 %0, t; }" : "=r"(a) : "l"(p));
    return a;
}
#define SWZ(x) ((x) ^ (((x) >> 3) & 0x70))

__device__ __forceinline__ void cp16(uint32_t dst, const void* src) {
    asm volatile("cp.async.cg.shared.global [%0], [%1], 16;"
                 :: "r"(dst), "l"(__cvta_generic_to_global(src)));
}
#define CP_COMMIT() asm volatile("cp.async.commit_group;" ::: "memory")
#define CP_WAIT(n)  asm volatile("cp.async.wait_group %0;" :: "n"(n) : "memory")

__device__ __forceinline__ void ldsm4(uint32_t* r, uint32_t addr) {
    asm volatile("ldmatrix.sync.aligned.m8n8.x4.shared.b16 {%0,%1,%2,%3}, [%4];"
                 : "=r"(r[0]), "=r"(r[1]), "=r"(r[2]), "=r"(r[3]) : "r"(addr));
}
__device__ __forceinline__ void mma16816(float* c, const uint32_t* a, uint32_t b0, uint32_t b1) {
    asm volatile("mma.sync.aligned.m16n8k16.row.col.f32.bf16.bf16.f32 "
                 "{%0,%1,%2,%3}, {%4,%5,%6,%7}, {%8,%9}, {%0,%1,%2,%3};"
                 : "+f"(c[0]), "+f"(c[1]), "+f"(c[2]), "+f"(c[3])
                 : "r"(a[0]), "r"(a[1]), "r"(a[2]), "r"(a[3]), "r"(b0), "r"(b1));
}
__device__ __forceinline__ void red_v4(float* dst, float a, float b, float c, float d) {
    asm volatile("red.global.add.v4.f32 [%0], {%1,%2,%3,%4};"
                 :: "l"(__cvta_generic_to_global(dst)), "f"(a), "f"(b), "f"(c), "f"(d) : "memory");
}

__device__ __forceinline__ void bf16_split(float v, __nv_bfloat16& hi, __nv_bfloat16& lo) {
    hi = __float2bfloat16(v);
    lo = __float2bfloat16(v - __bfloat162float(hi));
}

// ---------------- init (graph-replay safe zeroing) ----------------
__global__ void k_init() {
    int i = blockIdx.x * 256 + threadIdx.x;
    g_qupd[i] = 0.f;
    if (i < MM) { g_colsum[i] = 0.f; g_cmx[i] = 0.f; }
    if (i < 2) g_acc[i] = 0.f;
}

// ---------------- fused normalize + layout prep ----------------
__global__ void k_prep(const float* __restrict__ q, float* __restrict__ updq) {
    extern __shared__ float sp[];              // [512][33]
    float* red    = sp + 512 * 33;             // [8][32]
    float* invrow = red + 256;                 // [32]
    int b = blockIdx.y, hw0 = blockIdx.x * 32;
    int tx = threadIdx.x & 31, ty = threadIdx.x >> 5;

    const float* base = q + (size_t)b * 512 * 4096 + hw0 + tx;
    float s2 = 0.f;
#pragma unroll 8
    for (int i = 0; i < 64; i++) {
        int d = ty + 8 * i;
        float v = base[(size_t)d * 4096];
        sp[d * 33 + tx] = v;
        s2 += v * v;
    }
    red[ty * 32 + tx] = s2;
    __syncthreads();
    if (ty == 0) {
        float t = 0.f;
#pragma unroll
        for (int r = 0; r < 8; r++) t += red[r * 32 + tx];
        invrow[tx] = 1.0f / fmaxf(sqrtf(t), 1e-12f);
    }
    __syncthreads();
    float inv = invrow[tx];
    float* ubase = updq + (size_t)b * 1024 * 4096 + hw0 + tx;
#pragma unroll 8
    for (int i = 0; i < 64; i++) {
        int d = ty + 8 * i;
        float x = sp[d * 33 + tx] * inv;
        sp[d * 33 + tx] = x;
        ubase[(size_t)d * 4096] = x;
    }
    __syncthreads();
#pragma unroll 4
    for (int i = 0; i < 32; i++) {
        int idx = threadIdx.x + 256 * i;
        int nl = idx >> 8, dp = idx & 255;
        float x0 = sp[(2 * dp) * 33 + nl];
        float x1 = sp[(2 * dp + 1) * 33 + nl];
        __nv_bfloat16 h0, l0, h1, l1;
        bf16_split(x0, h0, l0);
        bf16_split(x1, h1, l1);
        size_t off = ((size_t)((b << 12) + hw0 + nl)) * 512 + 2 * dp;
        __nv_bfloat162 ph; ph.x = h0; ph.y = h1;
        __nv_bfloat162 pl; pl.x = l0; pl.y = l1;
        *(__nv_bfloat162*)(g_qbf_hi + off) = ph;
        *(__nv_bfloat162*)(g_qbf_lo + off) = pl;
    }
}

// keys -> bf16 hi/lo [m][d] + transposed [d][m] + per-key sum / norm^2
__global__ void k_prep_keys(const float* __restrict__ keys) {
    __shared__ float rs[512], rq[512];
    int m = blockIdx.x, d = threadIdx.x;
    float v = keys[m * 512 + d];
    __nv_bfloat16 hi, lo;
    bf16_split(v, hi, lo);
    g_keys_hi[m * 512 + d] = hi;
    g_keys_lo[m * 512 + d] = lo;
    g_keysT_hi[d * 512 + m] = hi;
    g_keysT_lo[d * 512 + m] = lo;
    rs[d] = v; rq[d] = v * v;
    __syncthreads();
    for (int s = 256; s > 0; s >>= 1) {
        if (d < s) { rs[d] += rs[d + s]; rq[d] += rq[d + s]; }
        __syncthreads();
    }
    if (d == 0) { g_sumk[m] = rs[0]; g_k2[m] = rq[0]; }
}

// ---------------- mma.sync GEMM: 128x128 tile, BK=32, hi|lo packed rows, 2 CTAs/SM ----------------
// smem row (128B) = [hi 64B | lo 64B] for 32 K-elems. SW128 swizzle unchanged.
#define OFS_A  0
#define OFS_B  16384
#define STAGE  32768

__global__ void __launch_bounds__(256, 2) k_mma_gemm(float* __restrict__ out, int mode) {
    extern __shared__ char smem[];
    uint32_t sb = smem_u32(smem);
    int tid = threadIdx.x;
    int col0 = blockIdx.x * 128;
    int n0   = blockIdx.y * 128;

    const __nv_bfloat16* Ahi = mode ? g_smbf_hi : g_qbf_hi;
    const __nv_bfloat16* Alo = mode ? g_smbf_lo : g_qbf_lo;
    const __nv_bfloat16* Bhi = mode ? g_keysT_hi : g_keys_hi;
    const __nv_bfloat16* Blo = mode ? g_keysT_lo : g_keys_lo;

    // stage: A/B tiles of 128 rows x 128B (hi|lo packed), k0 = elem offset
    auto load_stage = [&](int buf, int k0) {
        uint32_t base = sb + buf * STAGE;
#pragma unroll
        for (int i = 0; i < 4; i++) {
            int idx = tid + 256 * i;               // 1024 chunks for A
            int r = idx >> 3, c = idx & 7;
            uint32_t so = SWZ((uint32_t)(r * 128 + c * 16));
            if (c < 4) cp16(base + OFS_A + so, Ahi + (size_t)(n0 + r) * 512 + k0 + c * 8);
            else       cp16(base + OFS_A + so, Alo + (size_t)(n0 + r) * 512 + k0 + (c - 4) * 8);
        }
#pragma unroll
        for (int i = 0; i < 4; i++) {
            int idx = tid + 256 * i;
            int r = idx >> 3, c = idx & 7;
            uint32_t so = SWZ((uint32_t)(r * 128 + c * 16));
            if (c < 4) cp16(base + OFS_B + so, Bhi + (size_t)(col0 + r) * 512 + k0 + c * 8);
            else       cp16(base + OFS_B + so, Blo + (size_t)(col0 + r) * 512 + k0 + (c - 4) * 8);
        }
    };

    int lane = tid & 31;
    int wm = (tid >> 5) & 1;
    int wn = (tid >> 5) >> 1;
    int lrow = lane & 15, lhalf = lane >> 4;

    uint32_t arow[4], brow[2];
#pragma unroll
    for (int mf = 0; mf < 4; mf++) arow[mf] = (uint32_t)((wm * 64 + mf * 16 + lrow) * 128 + lhalf * 16);
#pragma unroll
    for (int ng = 0; ng < 2; ng++)  brow[ng] = (uint32_t)((wn * 32 + ng * 16 + lrow) * 128 + lhalf * 16);

    float C[4][4][4];
#pragma unroll
    for (int a = 0; a < 4; a++)
#pragma unroll
        for (int b = 0; b < 4; b++)
#pragma unroll
            for (int c = 0; c < 4; c++) C[a][b][c] = 0.f;

    load_stage(0, 0);   CP_COMMIT();
    load_stage(1, 32);  CP_COMMIT();

#pragma unroll 1
    for (int ch = 0; ch < 16; ch++) {
        if (ch < 15) { CP_WAIT(1); } else { CP_WAIT(0); }
        __syncthreads();
        uint32_t base = sb + (ch & 1) * STAGE;
#pragma unroll
        for (int ks = 0; ks < 2; ks++) {
            uint32_t kofs = (uint32_t)(ks * 32);   // bytes within hi half
            uint32_t ah[4][4], al[4][4];
#pragma unroll
            for (int mf = 0; mf < 4; mf++) {
                ldsm4(ah[mf], base + OFS_A + SWZ(arow[mf] + kofs));
                ldsm4(al[mf], base + OFS_A + SWZ(arow[mf] + kofs + 64));
            }
            uint32_t bh[2][4], bl[2][4];
#pragma unroll
            for (int ng = 0; ng < 2; ng++) {
                ldsm4(bh[ng], base + OFS_B + SWZ(brow[ng] + kofs));
                ldsm4(bl[ng], base + OFS_B + SWZ(brow[ng] + kofs + 64));
            }
            // term-major ordering, 3 terms (hh, hl, lh)
#pragma unroll
            for (int mf = 0; mf < 4; mf++)
#pragma unroll
                for (int nf = 0; nf < 4; nf++) {
                    int g = nf >> 1, h = nf & 1;
                    mma16816(C[mf][nf], ah[mf], bh[g][h], bh[g][h + 2]);
                }
#pragma unroll
            for (int mf = 0; mf < 4; mf++)
#pragma unroll
                for (int nf = 0; nf < 4; nf++) {
                    int g = nf >> 1, h = nf & 1;
                    mma16816(C[mf][nf], ah[mf], bl[g][h], bl[g][h + 2]);
                }
#pragma unroll
            for (int mf = 0; mf < 4; mf++)
#pragma unroll
                for (int nf = 0; nf < 4; nf++) {
                    int g = nf >> 1, h = nf & 1;
                    mma16816(C[mf][nf], al[mf], bh[g][h], bh[g][h + 2]);
                }
        }
        __syncthreads();
        if (ch < 14) { load_stage(ch & 1, (ch + 2) * 32); CP_COMMIT(); }
    }

    // epilogue: two 64-row passes through smem fs[64][132]
    float* fs = (float*)smem;
    int b = n0 >> 12, hw0 = n0 & 4095;
#pragma unroll 1
    for (int p = 0; p < 2; p++) {
        __syncthreads();
        if (wm == p) {
#pragma unroll
            for (int mf = 0; mf < 4; mf++) {
#pragma unroll
                for (int nf = 0; nf < 4; nf++) {
                    int gcol = wn * 32 + (nf >> 1) * 16 + (nf & 1) * 8 + 2 * (lane & 3);
                    int grow = mf * 16 + (lane >> 2);
                    *(float2*)&fs[grow * 132 + gcol]       = make_float2(C[mf][nf][0], C[mf][nf][1]);
                    *(float2*)&fs[(grow + 8) * 132 + gcol] = make_float2(C[mf][nf][2], C[mf][nf][3]);
                }
            }
        }
        __syncthreads();
        if (mode == 0) {
#pragma unroll 1
            for (int i = 0; i < 32; i++) {
                int idx = i * 256 + tid;
                int row = idx >> 7, col = idx & 127;
                out[(size_t)(n0 + p * 64 + row) * 512 + col0 + col] = fs[row * 132 + col];
            }
        } else {
#pragma unroll 1
            for (int i = 0; i < 32; i++) {
                int idx = i * 256 + tid;
                int c = idx >> 6, r = idx & 63;      // c: 0-127 chan, r: 0-63 row
                out[((size_t)(b * 1024 + 512 + col0 + c)) * 4096 + hw0 + p * 64 + r] = fs[r * 132 + c];
            }
        }
    }
}

// ---------------- fused: row softmax + column stats + exact top-2 refine ----------------
__device__ __forceinline__ void merge2(float& m1, int& i1, float& m2, int& i2,
                                       float b1, int bi1, float b2, int bi2) {
    if (b1 > m1 || (b1 == m1 && bi1 < i1)) {
        float om1 = m1; int oi1 = i1;
        m1 = b1; i1 = bi1;
        if (b2 > om1 || (b2 == om1 && bi2 < oi1)) { m2 = b2; i2 = bi2; }
        else { m2 = om1; i2 = oi1; }
    } else {
        if (b1 > m2 || (b1 == m2 && bi1 < i2)) { m2 = b1; i2 = bi1; }
    }
}

__global__ void k_rowsm(const float* __restrict__ S, float* __restrict__ SM,
                        const float* __restrict__ keys) {
    __shared__ float cbuf[8][512];
    int warp = threadIdx.x >> 5, lane = threadIdx.x & 31;
    int n = blockIdx.x * 8 + warp;
    const float* row = S + (size_t)n * MM;

    float orig[16], v[16];
    float m1 = -FLT_MAX, m2 = -FLT_MAX;
    int i1 = 0x7fffffff, i2 = 0x7fffffff;
#pragma unroll
    for (int j = 0; j < 16; j++) {
        float val = row[lane + 32 * j];
        orig[j] = val;
        int idx = lane + 32 * j;
        if (val > m1 || (val == m1 && idx < i1)) { m2 = m1; i2 = i1; m1 = val; i1 = idx; }
        else if (val > m2 || (val == m2 && idx < i2)) { m2 = val; i2 = idx; }
    }
#pragma unroll
    for (int off = 16; off; off >>= 1) {
        float b1 = __shfl_xor_sync(0xffffffffu, m1, off);
        int  bi1 = __shfl_xor_sync(0xffffffffu, i1, off);
        float b2 = __shfl_xor_sync(0xffffffffu, m2, off);
        int  bi2 = __shfl_xor_sync(0xffffffffu, i2, off);
        merge2(m1, i1, m2, i2, b1, bi1, b2, bi2);
    }
    float rmax = m1;
    float s = 0.f;
#pragma unroll
    for (int j = 0; j < 16; j++) {
        v[j] = expf(orig[j] - rmax);
        s += v[j];
    }
#pragma unroll
    for (int off = 16; off; off >>= 1) s += __shfl_xor_sync(0xffffffffu, s, off);
    float inv = 1.0f / s;
    float rme = expf(rmax);           // |score| <= ~23, safe in f32
    float* orow = SM + (size_t)n * MM;
#pragma unroll
    for (int j = 0; j < 16; j++) {
        float p = v[j] * inv;
        orow[lane + 32 * j] = p;
        __nv_bfloat16 hi, lo;
        bf16_split(p, hi, lo);
        g_smbf_hi[(size_t)n * 512 + lane + 32 * j] = hi;
        g_smbf_lo[(size_t)n * 512 + lane + 32 * j] = lo;
        cbuf[warp][lane + 32 * j] = v[j] * rme;   // = exp(s[n,m])
    }

    // ---- exact top-2 refinement (in-register candidates) ----
    float qv[16];
    {
        const __nv_bfloat16* qh = g_qbf_hi + (size_t)n * 512 + lane * 16;
        const __nv_bfloat16* ql = g_qbf_lo + (size_t)n * 512 + lane * 16;
#pragma unroll
        for (int i = 0; i < 16; i++)
            qv[i] = __bfloat162float(qh[i]) + __bfloat162float(ql[i]);
    }
    float sq = 0.f, q2 = 0.f;
#pragma unroll
    for (int i = 0; i < 16; i++) { sq += qv[i]; q2 += qv[i] * qv[i]; }
#pragma unroll
    for (int off = 16; off; off >>= 1) {
        sq += __shfl_xor_sync(0xffffffffu, sq, off);
        q2 += __shfl_xor_sync(0xffffffffu, q2, off);
    }
    float thr = m2 - 1e-3f;
    float e1 = -FLT_MAX, e2 = -FLT_MAX, s1g = 0.f;
    int t1 = 0x7fffffff, t2 = 0x7fffffff;
#pragma unroll 1
    for (int j = 0; j < 16; j++) {
        unsigned mask = __ballot_sync(0xffffffffu, orig[j] >= thr);
        while (mask) {
            int src = __ffs(mask) - 1;
            mask &= mask - 1;
            int m = src + 32 * j;
            float gs = __shfl_sync(0xffffffffu, orig[j], src);
            float d = 0.f;
            const float* kp = keys + (size_t)m * 512 + lane * 16;
#pragma unroll
            for (int i = 0; i < 16; i++) d += qv[i] * kp[i];
#pragma unroll
            for (int off = 16; off; off >>= 1) d += __shfl_xor_sync(0xffffffffu, d, off);
            if (d > e1 || (d == e1 && m < t1)) {
                e2 = e1; t2 = t1;
                e1 = d; t1 = m; s1g = gs;
            } else if (d > e2 || (d == e2 && m < t2)) {
                e2 = d; t2 = m;
            }
        }
    }
    if (lane == 0) {
        g_top1[n] = t1; g_top2[n] = t2;
        g_e1[n] = e1;   g_e2[n] = e2;
        g_s1g[n] = s1g;
        g_q2[n] = q2;   g_sumq[n] = sq;
    }

    __syncthreads();
    for (int c = threadIdx.x; c < 512; c += 256) {
        float cs = 0.f, cm = 0.f;
#pragma unroll
        for (int r = 0; r < 8; r++) {
            float x = cbuf[r][c];
            cs += x;
            cm = fmaxf(cm, x);
        }
        atomicAdd(&g_colsum[c], cs);
        atomicMax((int*)&g_cmx[c], __float_as_int(cm));   // positive floats: int-compare valid
    }
}

__global__ void k_colfin() {
    int c = threadIdx.x;
    g_colinv[c] = 1.0f / g_colsum[c];
}

// ---------------- per-pixel stats: wgt + compactness/separateness (analytic, exact dots) ----------------
__global__ void k_pixstats() {
    int n = blockIdx.x * 256 + threadIdx.x;
    int g1 = g_top1[n], g2 = g_top2[n];
    float e1 = g_e1[n], e2 = g_e2[n];
    float q2 = g_q2[n], sumq = g_sumq[n];

    g_wgt[n] = expf(g_s1g[n]) / g_cmx[g1];

    float cpos = q2 + g_k2[g1] - 2.0f * e1;
    float cneg = q2 + g_k2[g2] - 2.0f * e2;
    const float eps = 1e-6f;
    float dpos = sqrtf(fmaxf(cpos + 2.0f * eps * (sumq - g_sumk[g1]) + 512.0f * eps * eps, 0.f));
    float dneg = sqrtf(fmaxf(cneg + 2.0f * eps * (sumq - g_sumk[g2]) + 512.0f * eps * eps, 0.f));
    float hinge = fmaxf(dpos - dneg + 1.0f, 0.f);

    __shared__ float sc[256], sh[256];
    int t = threadIdx.x;
    sc[t] = cpos; sh[t] = hinge;
    __syncthreads();
    for (int s = 128; s > 0; s >>= 1) {
        if (t < s) { sc[t] += sc[t + s]; sh[t] += sh[t + s]; }
        __syncthreads();
    }
    if (t == 0) {
        atomicAdd(&g_acc[0], sc[0]);
        atomicAdd(&g_acc[1], sh[0]);
    }
}

// in-place transform raw scores -> s_query (|score| <= ~23 so exp is safe unshifted)
__global__ void k_sq(float* __restrict__ S) {
    long long idx = (long long)blockIdx.x * blockDim.x + threadIdx.x;
    int m = (int)(idx & 511);
    S[idx] = expf(S[idx]) * g_colinv[m];
}

// ---------------- segment sum (vector reductions) ----------------
__global__ void k_scatter(const float* __restrict__ qn) {
    int n = blockIdx.x * 256 + threadIdx.x;
    int b = n >> 12, hw = n & 4095;
    int g = g_top1[n];
    float w = g_wgt[n];
    const float* qp = qn + (size_t)b * 1024 * HW + hw;
    float* dst = g_qupd + (size_t)g * DD;
#pragma unroll 2
    for (int d = 0; d < DD; d += 4) {
        float a0 = w * qp[(size_t)(d + 0) * HW];
        float a1 = w * qp[(size_t)(d + 1) * HW];
        float a2 = w * qp[(size_t)(d + 2) * HW];
        float a3 = w * qp[(size_t)(d + 3) * HW];
        red_v4(dst + d, a0, a1, a2, a3);
    }
}

__global__ void k_updmem(const float* __restrict__ keys, float* __restrict__ out) {
    int m = blockIdx.x, t = threadIdx.x;
    float u[4];
    float s = 0.f;
#pragma unroll
    for (int r = 0; r < 4; r++) {
        int d = t + 128 * r;
        float x = g_qupd[(size_t)m * DD + d] + keys[(size_t)m * DD + d];
        u[r] = x;
        s += x * x;
    }
    __shared__ float red[128];
    red[t] = s;
    __syncthreads();
    for (int k = 64; k > 0; k >>= 1) {
        if (t < k) red[t] += red[t + k];
        __syncthreads();
    }
    float inv = 1.0f / fmaxf(sqrtf(red[0]), 1e-12f);
#pragma unroll
    for (int r = 0; r < 4; r++) {
        int d = t + 128 * r;
        out[OFF_UPDMEM + (size_t)m * DD + d] = u[r] * inv;
    }
}

__global__ void k_fin(float* __restrict__ out) {
    if (threadIdx.x == 0) {
        out[OFF_COMP] = (float)((double)g_acc[0] / ((double)NPIX * (double)DD));
        out[OFF_SEP]  = (float)((double)g_acc[1] / (double)NPIX);
    }
}

// ---------------- launch ----------------
#define GEMM_SMEM 65536
#define PREP_SMEM (512 * 33 * 4 + 256 * 4 + 32 * 4)

extern "C" void kernel_launch(void* const* d_in, const int* in_sizes, int n_in,
                              void* d_out, int out_size) {
    const float* query = (const float*)d_in[0];
    const float* keys  = (const float*)d_in[1];
    float* out  = (float*)d_out;
    float* updq = out + OFF_UPDQ;
    float* sq   = out + OFF_SQ;   // raw scores until k_sq transforms them
    float* sm   = out + OFF_SM;

    cudaFuncSetAttribute(k_mma_gemm, cudaFuncAttributeMaxDynamicSharedMemorySize, GEMM_SMEM);
    cudaFuncSetAttribute(k_prep, cudaFuncAttributeMaxDynamicSharedMemorySize, PREP_SMEM);

    k_init<<<(MM * DD) / 256, 256>>>();
    k_prep<<<dim3(HW / 32, BB), 256, PREP_SMEM>>>(query, updq);
    k_prep_keys<<<MM, DD>>>(keys);

    // GEMM1: raw scores S[n][m]
    k_mma_gemm<<<dim3(MM / 128, NPIX / 128), 256, GEMM_SMEM>>>(sq, 0);

    // fused row softmax + column stats + exact top-2
    k_rowsm<<<NPIX / 8, 256>>>(sq, sm, keys);
    k_colfin<<<1, 512>>>();

    k_pixstats<<<NPIX / 256, 256>>>();
    k_scatter<<<NPIX / 256, 256>>>(updq);
    k_sq<<<(int)(((long long)NPIX * MM) / 256), 256>>>(sq);

    // GEMM2: concat_mem -> upd_q second half
    k_mma_gemm<<<dim3(DD / 128, NPIX / 128), 256, GEMM_SMEM>>>(updq, 1);

    k_updmem<<<MM, 128>>>(keys, out);
    k_fin<<<1, 32>>>(out);
}